// round 1
// baseline (speedup 1.0000x reference)
#include <cuda_runtime.h>
#include <math.h>
#include <stdint.h>

#define B_ 4
#define T_ 1024
#define C_ 1024
#define H_ 16
#define HEAD_ 64
#define NTOK (B_*T_)

// ---------------- scratch (device globals; no allocation allowed) ----------------
__device__ float d_SX[NTOK*C_];
__device__ float d_XS[NTOK*C_];
__device__ float d_M1[NTOK*160];
__device__ float d_WX[NTOK*C_];
__device__ float d_KX[NTOK*C_];
__device__ float d_VX[NTOK*C_];
__device__ float d_RX[NTOK*C_];
__device__ float d_GX[NTOK*C_];
__device__ float d_R [NTOK*C_];
__device__ float d_K [NTOK*C_];
__device__ float d_V [NTOK*C_];
__device__ float d_G [NTOK*C_];
__device__ float d_Wd[NTOK*C_];
__device__ float d_WT[NTOK*64];
__device__ float d_Y [NTOK*C_];

// ---------------- prep: sx = shift(x) - x ; xs = x + sx * x_maa ----------------
__global__ void prep_kernel(const float* __restrict__ x, const float* __restrict__ xmaa,
                            float* __restrict__ SX, float* __restrict__ XS)
{
    int i4 = blockIdx.x * blockDim.x + threadIdx.x;
    int i  = i4 * 4;
    if (i >= NTOK * C_) return;
    int m = i >> 10;            // token index (C_ == 1024)
    int c = i & 1023;
    int t = m & (T_ - 1);
    float4 xv = *(const float4*)(x + i);
    float4 xp = make_float4(0.f, 0.f, 0.f, 0.f);
    if (t != 0) xp = *(const float4*)(x + i - C_);
    float4 ma = *(const float4*)(xmaa + c);
    float4 sx, xs;
    sx.x = xp.x - xv.x; sx.y = xp.y - xv.y; sx.z = xp.z - xv.z; sx.w = xp.w - xv.w;
    xs.x = fmaf(sx.x, ma.x, xv.x); xs.y = fmaf(sx.y, ma.y, xv.y);
    xs.z = fmaf(sx.z, ma.z, xv.z); xs.w = fmaf(sx.w, ma.w, xv.w);
    *(float4*)(SX + i) = sx;
    *(float4*)(XS + i) = xs;
}

// ---------------- generic fp32 tiled GEMM with epilogues ----------------
// C[M,N] = epi(A[M,K](lda) @ B[K,N])
// EPI: 0 none, 1 tanh, 2 silu, 3 mix: e0 + e1*(e2[n]+acc), 4 decay: exp(-exp(e2[n]+acc))
template<int EPI>
__global__ __launch_bounds__(256) void gemm_kernel(
    const float* __restrict__ A, int lda,
    const float* __restrict__ B,
    float* __restrict__ C,
    int M, int N, int K,
    const float* __restrict__ e0,
    const float* __restrict__ e1,
    const float* __restrict__ e2)
{
    const int BM = 128, BN = 128, BK = 16;
    __shared__ float As[BK][BM + 4];
    __shared__ float Bs[BK][BN + 4];
    int tid = threadIdx.x;
    int m0 = blockIdx.y * BM;
    int n0 = blockIdx.x * BN;
    int tx = tid & 15, ty = tid >> 4;

    int arow = tid >> 2;         // 0..63
    int acol = (tid & 3) << 2;   // 0,4,8,12
    int brow = tid >> 5;         // 0..7
    int bcol = (tid & 31) << 2;  // 0..124

    float acc[8][8];
    #pragma unroll
    for (int i = 0; i < 8; i++)
        #pragma unroll
        for (int j = 0; j < 8; j++) acc[i][j] = 0.f;

    for (int k0 = 0; k0 < K; k0 += BK) {
        #pragma unroll
        for (int i = 0; i < 2; i++) {
            int r = arow + i * 64;
            const float4 av = *(const float4*)(A + (size_t)(m0 + r) * lda + (k0 + acol));
            As[acol + 0][r] = av.x; As[acol + 1][r] = av.y;
            As[acol + 2][r] = av.z; As[acol + 3][r] = av.w;
        }
        #pragma unroll
        for (int i = 0; i < 2; i++) {
            int r = brow + i * 8;
            float4 bv = make_float4(0.f, 0.f, 0.f, 0.f);
            if (n0 + bcol < N)
                bv = *(const float4*)(B + (size_t)(k0 + r) * N + (n0 + bcol));
            *(float4*)&Bs[r][bcol] = bv;
        }
        __syncthreads();
        #pragma unroll
        for (int kk = 0; kk < BK; kk++) {
            float a[8], b[8];
            *(float4*)&a[0] = *(const float4*)&As[kk][ty * 8];
            *(float4*)&a[4] = *(const float4*)&As[kk][ty * 8 + 4];
            *(float4*)&b[0] = *(const float4*)&Bs[kk][tx * 8];
            *(float4*)&b[4] = *(const float4*)&Bs[kk][tx * 8 + 4];
            #pragma unroll
            for (int i = 0; i < 8; i++)
                #pragma unroll
                for (int j = 0; j < 8; j++)
                    acc[i][j] = fmaf(a[i], b[j], acc[i][j]);
        }
        __syncthreads();
    }

    #pragma unroll
    for (int i = 0; i < 8; i++) {
        int m = m0 + ty * 8 + i;
        #pragma unroll
        for (int j = 0; j < 8; j++) {
            int n = n0 + tx * 8 + j;
            if (n < N) {
                float v = acc[i][j];
                float o;
                if (EPI == 0)      o = v;
                else if (EPI == 1) o = tanhf(v);
                else if (EPI == 2) o = v / (1.f + expf(-v));
                else if (EPI == 3) { size_t idx = (size_t)m * N + n; o = fmaf(e1[idx], e2[n] + v, e0[idx]); }
                else               o = expf(-expf(e2[n] + v));
                C[(size_t)m * N + n] = o;
            }
        }
    }
}

// ---------------- WKV scan + fused /8, groupnorm, ln affine, gate ----------------
// grid: 64 blocks (b,h). 256 threads: tid = kq*64 + v ; each thread owns state[k in kq*16..+16][v]
__global__ __launch_bounds__(256) void scan_kernel(
    const float* __restrict__ R, const float* __restrict__ Kt,
    const float* __restrict__ V, const float* __restrict__ W,
    const float* __restrict__ G, const float* __restrict__ u,
    const float* __restrict__ lnw, const float* __restrict__ lnb,
    float* __restrict__ Y)
{
    int bh = blockIdx.x;
    int b = bh >> 4, h = bh & 15;
    int tid = threadIdx.x;
    int v = tid & 63, kq = tid >> 6;

    __shared__ float r_s[64], k_s[64], w_s[64], v_s[64], g_s[64], u_s[64];
    __shared__ float red[256];
    __shared__ float sred[4];

    if (tid < 64) u_s[tid] = u[h * 64 + tid];

    float state[16];
    #pragma unroll
    for (int i = 0; i < 16; i++) state[i] = 0.f;

    const size_t base_bh = (size_t)b * T_ * C_ + (size_t)h * 64;

    // prefetch t = 0
    float pre, gpre = 0.f;
    {
        size_t idx = base_bh + v;
        pre = (kq == 0) ? R[idx] : (kq == 1) ? Kt[idx] : (kq == 2) ? W[idx] : V[idx];
        if (kq == 0) gpre = G[idx];
    }

    for (int t = 0; t < T_; ++t) {
        if (kq == 0) { r_s[v] = pre; g_s[v] = gpre; }
        else if (kq == 1) k_s[v] = pre;
        else if (kq == 2) w_s[v] = pre;
        else              v_s[v] = pre;
        __syncthreads();

        if (t < T_ - 1) {
            size_t idx = base_bh + (size_t)(t + 1) * C_ + v;
            pre = (kq == 0) ? R[idx] : (kq == 1) ? Kt[idx] : (kq == 2) ? W[idx] : V[idx];
            if (kq == 0) gpre = G[idx];
        }

        float vv = v_s[v];
        float y = 0.f;
        #pragma unroll
        for (int i = 0; i < 16; i++) {
            int kk = kq * 16 + i;
            float a = k_s[kk] * vv;
            y = fmaf(r_s[kk], fmaf(u_s[kk], a, state[i]), y);
            state[i] = fmaf(w_s[kk], state[i], a);
        }
        red[tid] = y;
        __syncthreads();

        float yd = 0.f;
        if (kq == 0) {
            float ys = (red[v] + red[64 + v]) + (red[128 + v] + red[192 + v]);
            yd = ys * 0.125f;
            float s1 = yd, s2 = yd * yd;
            #pragma unroll
            for (int o = 16; o > 0; o >>= 1) {
                s1 += __shfl_xor_sync(0xffffffffu, s1, o);
                s2 += __shfl_xor_sync(0xffffffffu, s2, o);
            }
            int w2 = v >> 5;
            if ((v & 31) == 0) { sred[w2 * 2] = s1; sred[w2 * 2 + 1] = s2; }
        }
        __syncthreads();

        if (kq == 0) {
            float sum   = sred[0] + sred[2];
            float sumsq = sred[1] + sred[3];
            float mean = sum * (1.f / 64.f);
            float var  = sumsq * (1.f / 64.f) - mean * mean;
            float o = (yd - mean) * rsqrtf(var + 1e-5f);
            int c = h * 64 + v;
            o = fmaf(o, lnw[c], lnb[c]);
            o *= g_s[v];
            Y[base_bh + (size_t)t * C_ + v] = o;
        }
        // next iteration's shared writes are ordered by the t+1 top barrier
    }
}

// ---------------- launch ----------------
extern "C" void kernel_launch(void* const* d_in, const int* in_sizes, int n_in,
                              void* d_out, int out_size)
{
    (void)in_sizes; (void)n_in; (void)out_size;
    const float* x          = (const float*)d_in[0];
    const float* x_maa      = (const float*)d_in[1];
    const float* w_maa      = (const float*)d_in[2];
    const float* k_maa      = (const float*)d_in[3];
    const float* v_maa      = (const float*)d_in[4];
    const float* r_maa      = (const float*)d_in[5];
    const float* g_maa      = (const float*)d_in[6];
    const float* tm_w1      = (const float*)d_in[7];
    const float* tm_w2      = (const float*)d_in[8];
    const float* td_w1      = (const float*)d_in[9];
    const float* td_w2      = (const float*)d_in[10];
    const float* time_decay = (const float*)d_in[11];
    const float* time_first = (const float*)d_in[12];
    const float* Wr         = (const float*)d_in[13];
    const float* Wk         = (const float*)d_in[14];
    const float* Wv         = (const float*)d_in[15];
    const float* Wg         = (const float*)d_in[16];
    const float* Wo         = (const float*)d_in[17];
    const float* ln_w       = (const float*)d_in[18];
    const float* ln_b       = (const float*)d_in[19];
    float* out = (float*)d_out;

    float *SX, *XS, *M1, *WX, *KX, *VX, *RX, *GX, *Rb, *Kb, *Vb, *Gb, *Wd, *WT, *Yb;
    cudaGetSymbolAddress((void**)&SX, d_SX);
    cudaGetSymbolAddress((void**)&XS, d_XS);
    cudaGetSymbolAddress((void**)&M1, d_M1);
    cudaGetSymbolAddress((void**)&WX, d_WX);
    cudaGetSymbolAddress((void**)&KX, d_KX);
    cudaGetSymbolAddress((void**)&VX, d_VX);
    cudaGetSymbolAddress((void**)&RX, d_RX);
    cudaGetSymbolAddress((void**)&GX, d_GX);
    cudaGetSymbolAddress((void**)&Rb, d_R);
    cudaGetSymbolAddress((void**)&Kb, d_K);
    cudaGetSymbolAddress((void**)&Vb, d_V);
    cudaGetSymbolAddress((void**)&Gb, d_G);
    cudaGetSymbolAddress((void**)&Wd, d_Wd);
    cudaGetSymbolAddress((void**)&WT, d_WT);
    cudaGetSymbolAddress((void**)&Yb, d_Y);

    dim3 blk(256);

    // 1. prep
    prep_kernel<<<(NTOK * C_ / 4 + 255) / 256, blk>>>(x, x_maa, SX, XS);

    // 2. M1 = tanh(XS @ tm_w1)   [4096,160]
    gemm_kernel<1><<<dim3(2, 32), blk>>>(XS, C_, tm_w1, M1, NTOK, 160, C_,
                                         nullptr, nullptr, nullptr);

    // 3. five mixed inputs: out_f = x + sx*(maa_f + M1[:,f*32:+32] @ tm_w2[f])
    const float* maas[5]  = {w_maa, k_maa, v_maa, r_maa, g_maa};
    float*       mouts[5] = {WX, KX, VX, RX, GX};
    for (int f = 0; f < 5; f++)
        gemm_kernel<3><<<dim3(8, 32), blk>>>(M1 + f * 32, 160, tm_w2 + (size_t)f * 32 * C_,
                                             mouts[f], NTOK, C_, 32, x, SX, maas[f]);

    // 4. projections
    gemm_kernel<0><<<dim3(8, 32), blk>>>(RX, C_, Wr, Rb, NTOK, C_, C_, nullptr, nullptr, nullptr);
    gemm_kernel<0><<<dim3(8, 32), blk>>>(KX, C_, Wk, Kb, NTOK, C_, C_, nullptr, nullptr, nullptr);
    gemm_kernel<0><<<dim3(8, 32), blk>>>(VX, C_, Wv, Vb, NTOK, C_, C_, nullptr, nullptr, nullptr);
    gemm_kernel<2><<<dim3(8, 32), blk>>>(GX, C_, Wg, Gb, NTOK, C_, C_, nullptr, nullptr, nullptr);

    // 5. decay LoRA: WT = tanh(WX @ td_w1); Wd = exp(-exp(time_decay + WT @ td_w2))
    gemm_kernel<1><<<dim3(1, 32), blk>>>(WX, C_, td_w1, WT, NTOK, 64, C_, nullptr, nullptr, nullptr);
    gemm_kernel<4><<<dim3(8, 32), blk>>>(WT, 64, td_w2, Wd, NTOK, C_, 64, nullptr, nullptr, time_decay);

    // 6. WKV scan + groupnorm + gate
    scan_kernel<<<64, blk>>>(Rb, Kb, Vb, Wd, Gb, time_first, ln_w, ln_b, Yb);

    // 7. output projection
    gemm_kernel<0><<<dim3(8, 32), blk>>>(Yb, C_, Wo, out, NTOK, C_, C_, nullptr, nullptr, nullptr);
}

// round 2
// speedup vs baseline: 1.1727x; 1.1727x over previous
#include <cuda_runtime.h>
#include <mma.h>
#include <math.h>
#include <stdint.h>

using namespace nvcuda;

#define B_ 4
#define T_ 1024
#define C_ 1024
#define H_ 16
#define HEAD_ 64
#define NTOK (B_*T_)

// ---------------- scratch (device globals; no allocation allowed) ----------------
__device__ float d_SX[NTOK*C_];
__device__ float d_XS[NTOK*C_];
__device__ float d_M1[NTOK*160];
__device__ float d_WX[NTOK*C_];
__device__ float d_KX[NTOK*C_];
__device__ float d_VX[NTOK*C_];
__device__ float d_RX[NTOK*C_];
__device__ float d_GX[NTOK*C_];
__device__ float d_R [NTOK*C_];
__device__ float d_K [NTOK*C_];
__device__ float d_V [NTOK*C_];
__device__ float d_G [NTOK*C_];
__device__ float d_Wd[NTOK*C_];
__device__ float d_WT[NTOK*64];
__device__ float d_Y [NTOK*C_];

// ---------------- prep: sx = shift(x) - x ; xs = x + sx * x_maa ----------------
__global__ void prep_kernel(const float* __restrict__ x, const float* __restrict__ xmaa,
                            float* __restrict__ SX, float* __restrict__ XS)
{
    int i4 = blockIdx.x * blockDim.x + threadIdx.x;
    int i  = i4 * 4;
    if (i >= NTOK * C_) return;
    int m = i >> 10;            // token index (C_ == 1024)
    int c = i & 1023;
    int t = m & (T_ - 1);
    float4 xv = *(const float4*)(x + i);
    float4 xp = make_float4(0.f, 0.f, 0.f, 0.f);
    if (t != 0) xp = *(const float4*)(x + i - C_);
    float4 ma = *(const float4*)(xmaa + c);
    float4 sx, xs;
    sx.x = xp.x - xv.x; sx.y = xp.y - xv.y; sx.z = xp.z - xv.z; sx.w = xp.w - xv.w;
    xs.x = fmaf(sx.x, ma.x, xv.x); xs.y = fmaf(sx.y, ma.y, xv.y);
    xs.z = fmaf(sx.z, ma.z, xv.z); xs.w = fmaf(sx.w, ma.w, xv.w);
    *(float4*)(SX + i) = sx;
    *(float4*)(XS + i) = xs;
}

// ---------------- generic fp32 tiled GEMM with epilogues (small/skinny GEMMs) ----------------
// C[M,N] = epi(A[M,K](lda) @ B[K,N])
// EPI: 0 none, 1 tanh, 2 silu, 3 mix: e0 + e1*(e2[n]+acc), 4 decay: exp(-exp(e2[n]+acc))
template<int EPI>
__global__ __launch_bounds__(256) void gemm_kernel(
    const float* __restrict__ A, int lda,
    const float* __restrict__ B,
    float* __restrict__ C,
    int M, int N, int K,
    const float* __restrict__ e0,
    const float* __restrict__ e1,
    const float* __restrict__ e2)
{
    const int BM = 128, BN = 128, BK = 16;
    __shared__ float As[BK][BM + 4];
    __shared__ float Bs[BK][BN + 4];
    int tid = threadIdx.x;
    int m0 = blockIdx.y * BM;
    int n0 = blockIdx.x * BN;
    int tx = tid & 15, ty = tid >> 4;

    int arow = tid >> 2;         // 0..63
    int acol = (tid & 3) << 2;   // 0,4,8,12
    int brow = tid >> 5;         // 0..7
    int bcol = (tid & 31) << 2;  // 0..124

    float acc[8][8];
    #pragma unroll
    for (int i = 0; i < 8; i++)
        #pragma unroll
        for (int j = 0; j < 8; j++) acc[i][j] = 0.f;

    for (int k0 = 0; k0 < K; k0 += BK) {
        #pragma unroll
        for (int i = 0; i < 2; i++) {
            int r = arow + i * 64;
            const float4 av = *(const float4*)(A + (size_t)(m0 + r) * lda + (k0 + acol));
            As[acol + 0][r] = av.x; As[acol + 1][r] = av.y;
            As[acol + 2][r] = av.z; As[acol + 3][r] = av.w;
        }
        #pragma unroll
        for (int i = 0; i < 2; i++) {
            int r = brow + i * 8;
            float4 bv = make_float4(0.f, 0.f, 0.f, 0.f);
            if (n0 + bcol < N)
                bv = *(const float4*)(B + (size_t)(k0 + r) * N + (n0 + bcol));
            *(float4*)&Bs[r][bcol] = bv;
        }
        __syncthreads();
        #pragma unroll
        for (int kk = 0; kk < BK; kk++) {
            float a[8], b[8];
            *(float4*)&a[0] = *(const float4*)&As[kk][ty * 8];
            *(float4*)&a[4] = *(const float4*)&As[kk][ty * 8 + 4];
            *(float4*)&b[0] = *(const float4*)&Bs[kk][tx * 8];
            *(float4*)&b[4] = *(const float4*)&Bs[kk][tx * 8 + 4];
            #pragma unroll
            for (int i = 0; i < 8; i++)
                #pragma unroll
                for (int j = 0; j < 8; j++)
                    acc[i][j] = fmaf(a[i], b[j], acc[i][j]);
        }
        __syncthreads();
    }

    #pragma unroll
    for (int i = 0; i < 8; i++) {
        int m = m0 + ty * 8 + i;
        #pragma unroll
        for (int j = 0; j < 8; j++) {
            int n = n0 + tx * 8 + j;
            if (n < N) {
                float v = acc[i][j];
                float o;
                if (EPI == 0)      o = v;
                else if (EPI == 1) o = tanhf(v);
                else if (EPI == 2) o = v / (1.f + expf(-v));
                else if (EPI == 3) { size_t idx = (size_t)m * N + n; o = fmaf(e1[idx], e2[n] + v, e0[idx]); }
                else               o = expf(-expf(e2[n] + v));
                C[(size_t)m * N + n] = o;
            }
        }
    }
}

// ---------------- tf32 tensor-core GEMM (big 1024x1024-weight projections) ----------------
// C[M,N] = epi(A[M,K] @ B[K,N]), A packed (lda=K), M%128==0, N%128==0, K%16==0.
// EPI: 0 none, 2 silu
template<int EPI>
__global__ __launch_bounds__(256) void wmma_gemm(
    const float* __restrict__ A,
    const float* __restrict__ B,
    float* __restrict__ C,
    int M, int N, int K)
{
    const int BM = 128, BN = 128, BK = 16;
    __shared__ float As[BK][BM + 4];   // As[k][m]  (A^T) -> col_major fragment, ld = 132
    __shared__ float Bs[BK][BN + 4];   // Bs[k][n]        -> row_major fragment, ld = 132
    __shared__ float stage[8][16][20]; // per-warp epilogue staging

    int tid = threadIdx.x;
    int wid = tid >> 5;
    int lane = tid & 31;
    int wm = wid >> 2;        // 0..1  (64-row slab)
    int wn = wid & 3;         // 0..3  (32-col slab)
    int m0 = blockIdx.y * BM;
    int n0 = blockIdx.x * BN;

    int arow = tid >> 2;          // 0..63
    int acol = (tid & 3) << 2;    // 0,4,8,12
    int brow = tid >> 5;          // 0..7
    int bcol = (tid & 31) << 2;   // 0..124

    wmma::fragment<wmma::accumulator, 16, 16, 8, float> acc[4][2];
    #pragma unroll
    for (int i = 0; i < 4; i++)
        #pragma unroll
        for (int j = 0; j < 2; j++) wmma::fill_fragment(acc[i][j], 0.f);

    for (int k0 = 0; k0 < K; k0 += BK) {
        #pragma unroll
        for (int i = 0; i < 2; i++) {
            int r = arow + i * 64;
            const float4 av = *(const float4*)(A + (size_t)(m0 + r) * K + (k0 + acol));
            As[acol + 0][r] = av.x; As[acol + 1][r] = av.y;
            As[acol + 2][r] = av.z; As[acol + 3][r] = av.w;
        }
        #pragma unroll
        for (int i = 0; i < 2; i++) {
            int r = brow + i * 8;
            float4 bv = *(const float4*)(B + (size_t)(k0 + r) * N + (n0 + bcol));
            *(float4*)&Bs[r][bcol] = bv;
        }
        __syncthreads();

        #pragma unroll
        for (int kk = 0; kk < BK; kk += 8) {
            wmma::fragment<wmma::matrix_a, 16, 16, 8, wmma::precision::tf32, wmma::col_major> af[4];
            wmma::fragment<wmma::matrix_b, 16, 16, 8, wmma::precision::tf32, wmma::row_major> bf[2];
            #pragma unroll
            for (int i = 0; i < 4; i++) {
                wmma::load_matrix_sync(af[i], &As[kk][wm * 64 + i * 16], BM + 4);
                #pragma unroll
                for (int t = 0; t < af[i].num_elements; t++)
                    af[i].x[t] = wmma::__float_to_tf32(af[i].x[t]);
            }
            #pragma unroll
            for (int j = 0; j < 2; j++) {
                wmma::load_matrix_sync(bf[j], &Bs[kk][wn * 32 + j * 16], BN + 4);
                #pragma unroll
                for (int t = 0; t < bf[j].num_elements; t++)
                    bf[j].x[t] = wmma::__float_to_tf32(bf[j].x[t]);
            }
            #pragma unroll
            for (int i = 0; i < 4; i++)
                #pragma unroll
                for (int j = 0; j < 2; j++)
                    wmma::mma_sync(acc[i][j], af[i], bf[j], acc[i][j]);
        }
        __syncthreads();
    }

    #pragma unroll
    for (int i = 0; i < 4; i++) {
        #pragma unroll
        for (int j = 0; j < 2; j++) {
            int mb = m0 + wm * 64 + i * 16;
            int nb = n0 + wn * 32 + j * 16;
            if (EPI == 0) {
                wmma::store_matrix_sync(C + (size_t)mb * N + nb, acc[i][j], N, wmma::mem_row_major);
            } else {
                wmma::store_matrix_sync(&stage[wid][0][0], acc[i][j], 20, wmma::mem_row_major);
                __syncwarp();
                int r  = lane >> 1;
                int c0 = (lane & 1) * 8;
                #pragma unroll
                for (int q = 0; q < 8; q++) {
                    float v = stage[wid][r][c0 + q];
                    float o = v / (1.f + expf(-v));   // silu
                    C[(size_t)(mb + r) * N + (nb + c0 + q)] = o;
                }
                __syncwarp();
            }
        }
    }
}

// ---------------- WKV scan + fused /8, groupnorm, ln affine, gate ----------------
// grid: 64 blocks (b,h). 256 threads: tid = kq*64 + v ; each thread owns state[k in kq*16..+16][v]
__global__ __launch_bounds__(256) void scan_kernel(
    const float* __restrict__ R, const float* __restrict__ Kt,
    const float* __restrict__ V, const float* __restrict__ W,
    const float* __restrict__ G, const float* __restrict__ u,
    const float* __restrict__ lnw, const float* __restrict__ lnb,
    float* __restrict__ Y)
{
    int bh = blockIdx.x;
    int b = bh >> 4, h = bh & 15;
    int tid = threadIdx.x;
    int v = tid & 63, kq = tid >> 6;

    __shared__ float r_s[64], k_s[64], w_s[64], v_s[64], g_s[64], u_s[64];
    __shared__ float red[256];
    __shared__ float sred[4];

    if (tid < 64) u_s[tid] = u[h * 64 + tid];

    float state[16];
    #pragma unroll
    for (int i = 0; i < 16; i++) state[i] = 0.f;

    const size_t base_bh = (size_t)b * T_ * C_ + (size_t)h * 64;

    // prefetch t = 0
    float pre, gpre = 0.f;
    {
        size_t idx = base_bh + v;
        pre = (kq == 0) ? R[idx] : (kq == 1) ? Kt[idx] : (kq == 2) ? W[idx] : V[idx];
        if (kq == 0) gpre = G[idx];
    }

    for (int t = 0; t < T_; ++t) {
        if (kq == 0) { r_s[v] = pre; g_s[v] = gpre; }
        else if (kq == 1) k_s[v] = pre;
        else if (kq == 2) w_s[v] = pre;
        else              v_s[v] = pre;
        __syncthreads();

        if (t < T_ - 1) {
            size_t idx = base_bh + (size_t)(t + 1) * C_ + v;
            pre = (kq == 0) ? R[idx] : (kq == 1) ? Kt[idx] : (kq == 2) ? W[idx] : V[idx];
            if (kq == 0) gpre = G[idx];
        }

        float vv = v_s[v];
        float y = 0.f;
        #pragma unroll
        for (int i = 0; i < 16; i++) {
            int kk = kq * 16 + i;
            float a = k_s[kk] * vv;
            y = fmaf(r_s[kk], fmaf(u_s[kk], a, state[i]), y);
            state[i] = fmaf(w_s[kk], state[i], a);
        }
        red[tid] = y;
        __syncthreads();

        float yd = 0.f;
        if (kq == 0) {
            float ys = (red[v] + red[64 + v]) + (red[128 + v] + red[192 + v]);
            yd = ys * 0.125f;
            float s1 = yd, s2 = yd * yd;
            #pragma unroll
            for (int o = 16; o > 0; o >>= 1) {
                s1 += __shfl_xor_sync(0xffffffffu, s1, o);
                s2 += __shfl_xor_sync(0xffffffffu, s2, o);
            }
            int w2 = v >> 5;
            if ((v & 31) == 0) { sred[w2 * 2] = s1; sred[w2 * 2 + 1] = s2; }
        }
        __syncthreads();

        if (kq == 0) {
            float sum   = sred[0] + sred[2];
            float sumsq = sred[1] + sred[3];
            float mean = sum * (1.f / 64.f);
            float var  = sumsq * (1.f / 64.f) - mean * mean;
            float o = (yd - mean) * rsqrtf(var + 1e-5f);
            int c = h * 64 + v;
            o = fmaf(o, lnw[c], lnb[c]);
            o *= g_s[v];
            Y[base_bh + (size_t)t * C_ + v] = o;
        }
    }
}

// ---------------- launch ----------------
extern "C" void kernel_launch(void* const* d_in, const int* in_sizes, int n_in,
                              void* d_out, int out_size)
{
    (void)in_sizes; (void)n_in; (void)out_size;
    const float* x          = (const float*)d_in[0];
    const float* x_maa      = (const float*)d_in[1];
    const float* w_maa      = (const float*)d_in[2];
    const float* k_maa      = (const float*)d_in[3];
    const float* v_maa      = (const float*)d_in[4];
    const float* r_maa      = (const float*)d_in[5];
    const float* g_maa      = (const float*)d_in[6];
    const float* tm_w1      = (const float*)d_in[7];
    const float* tm_w2      = (const float*)d_in[8];
    const float* td_w1      = (const float*)d_in[9];
    const float* td_w2      = (const float*)d_in[10];
    const float* time_decay = (const float*)d_in[11];
    const float* time_first = (const float*)d_in[12];
    const float* Wr         = (const float*)d_in[13];
    const float* Wk         = (const float*)d_in[14];
    const float* Wv         = (const float*)d_in[15];
    const float* Wg         = (const float*)d_in[16];
    const float* Wo         = (const float*)d_in[17];
    const float* ln_w       = (const float*)d_in[18];
    const float* ln_b       = (const float*)d_in[19];
    float* out = (float*)d_out;

    float *SX, *XS, *M1, *WX, *KX, *VX, *RX, *GX, *Rb, *Kb, *Vb, *Gb, *Wd, *WT, *Yb;
    cudaGetSymbolAddress((void**)&SX, d_SX);
    cudaGetSymbolAddress((void**)&XS, d_XS);
    cudaGetSymbolAddress((void**)&M1, d_M1);
    cudaGetSymbolAddress((void**)&WX, d_WX);
    cudaGetSymbolAddress((void**)&KX, d_KX);
    cudaGetSymbolAddress((void**)&VX, d_VX);
    cudaGetSymbolAddress((void**)&RX, d_RX);
    cudaGetSymbolAddress((void**)&GX, d_GX);
    cudaGetSymbolAddress((void**)&Rb, d_R);
    cudaGetSymbolAddress((void**)&Kb, d_K);
    cudaGetSymbolAddress((void**)&Vb, d_V);
    cudaGetSymbolAddress((void**)&Gb, d_G);
    cudaGetSymbolAddress((void**)&Wd, d_Wd);
    cudaGetSymbolAddress((void**)&WT, d_WT);
    cudaGetSymbolAddress((void**)&Yb, d_Y);

    dim3 blk(256);

    // 1. prep
    prep_kernel<<<(NTOK * C_ / 4 + 255) / 256, blk>>>(x, x_maa, SX, XS);

    // 2. M1 = tanh(XS @ tm_w1)   [4096,160]
    gemm_kernel<1><<<dim3(2, 32), blk>>>(XS, C_, tm_w1, M1, NTOK, 160, C_,
                                         nullptr, nullptr, nullptr);

    // 3. five mixed inputs: out_f = x + sx*(maa_f + M1[:,f*32:+32] @ tm_w2[f])
    const float* maas[5]  = {w_maa, k_maa, v_maa, r_maa, g_maa};
    float*       mouts[5] = {WX, KX, VX, RX, GX};
    for (int f = 0; f < 5; f++)
        gemm_kernel<3><<<dim3(8, 32), blk>>>(M1 + f * 32, 160, tm_w2 + (size_t)f * 32 * C_,
                                             mouts[f], NTOK, C_, 32, x, SX, maas[f]);

    // 4. projections (tf32 tensor core)
    wmma_gemm<0><<<dim3(8, 32), blk>>>(RX, Wr, Rb, NTOK, C_, C_);
    wmma_gemm<0><<<dim3(8, 32), blk>>>(KX, Wk, Kb, NTOK, C_, C_);
    wmma_gemm<0><<<dim3(8, 32), blk>>>(VX, Wv, Vb, NTOK, C_, C_);
    wmma_gemm<2><<<dim3(8, 32), blk>>>(GX, Wg, Gb, NTOK, C_, C_);

    // 5. decay LoRA: WT = tanh(WX @ td_w1); Wd = exp(-exp(time_decay + WT @ td_w2))
    gemm_kernel<1><<<dim3(1, 32), blk>>>(WX, C_, td_w1, WT, NTOK, 64, C_, nullptr, nullptr, nullptr);
    gemm_kernel<4><<<dim3(8, 32), blk>>>(WT, 64, td_w2, Wd, NTOK, C_, 64, nullptr, nullptr, time_decay);

    // 6. WKV scan + groupnorm + gate
    scan_kernel<<<64, blk>>>(Rb, Kb, Vb, Wd, Gb, time_first, ln_w, ln_b, Yb);

    // 7. output projection (tf32 tensor core)
    wmma_gemm<0><<<dim3(8, 32), blk>>>(Yb, Wo, out, NTOK, C_, C_);
}

// round 3
// speedup vs baseline: 1.2820x; 1.0932x over previous
#include <cuda_runtime.h>
#include <mma.h>
#include <math.h>
#include <stdint.h>

using namespace nvcuda;

#define B_ 4
#define T_ 1024
#define C_ 1024
#define H_ 16
#define NTOK (B_*T_)

// ---------------- scratch (device globals; no allocation allowed) ----------------
__device__ float d_SX[NTOK*C_];
__device__ float d_XS[NTOK*C_];
__device__ float d_M1[NTOK*160];
__device__ float d_WX[NTOK*C_];
__device__ float d_KX[NTOK*C_];
__device__ float d_VX[NTOK*C_];
__device__ float d_RX[NTOK*C_];
__device__ float d_GX[NTOK*C_];
__device__ float d_R [NTOK*C_];
__device__ float d_K [NTOK*C_];
__device__ float d_V [NTOK*C_];
__device__ float d_G [NTOK*C_];
__device__ float d_Wd[NTOK*C_];
__device__ float d_WT[NTOK*64];
__device__ float d_Y [NTOK*C_];

// ---------------- cp.async helpers ----------------
__device__ __forceinline__ void cp_async16(uint32_t dst, const void* src) {
    asm volatile("cp.async.cg.shared.global [%0], [%1], 16;\n" :: "r"(dst), "l"(src));
}
__device__ __forceinline__ void cp_commit() { asm volatile("cp.async.commit_group;\n"); }
template<int N> __device__ __forceinline__ void cp_wait() {
    asm volatile("cp.async.wait_group %0;\n" :: "n"(N));
}

// ---------------- prep: sx = shift(x) - x ; xs = x + sx * x_maa ----------------
__global__ void prep_kernel(const float* __restrict__ x, const float* __restrict__ xmaa,
                            float* __restrict__ SX, float* __restrict__ XS)
{
    int i4 = blockIdx.x * blockDim.x + threadIdx.x;
    int i  = i4 * 4;
    if (i >= NTOK * C_) return;
    int m = i >> 10;
    int c = i & 1023;
    int t = m & (T_ - 1);
    float4 xv = *(const float4*)(x + i);
    float4 xp = make_float4(0.f, 0.f, 0.f, 0.f);
    if (t != 0) xp = *(const float4*)(x + i - C_);
    float4 ma = *(const float4*)(xmaa + c);
    float4 sx, xs;
    sx.x = xp.x - xv.x; sx.y = xp.y - xv.y; sx.z = xp.z - xv.z; sx.w = xp.w - xv.w;
    xs.x = fmaf(sx.x, ma.x, xv.x); xs.y = fmaf(sx.y, ma.y, xv.y);
    xs.z = fmaf(sx.z, ma.z, xv.z); xs.w = fmaf(sx.w, ma.w, xv.w);
    *(float4*)(SX + i) = sx;
    *(float4*)(XS + i) = xs;
}

// ---------------- generic fp32 tiled GEMM with epilogues (skinny GEMMs) ----------------
// EPI: 1 tanh, 4 decay: exp(-exp(e2[n]+acc))
template<int EPI>
__global__ __launch_bounds__(256) void gemm_kernel(
    const float* __restrict__ A, int lda,
    const float* __restrict__ B,
    float* __restrict__ C,
    int M, int N, int K,
    const float* __restrict__ e2)
{
    const int BM = 128, BN = 128, BK = 16;
    __shared__ float As[BK][BM + 4];
    __shared__ float Bs[BK][BN + 4];
    int tid = threadIdx.x;
    int m0 = blockIdx.y * BM;
    int n0 = blockIdx.x * BN;
    int tx = tid & 15, ty = tid >> 4;

    int arow = tid >> 2;
    int acol = (tid & 3) << 2;
    int brow = tid >> 5;
    int bcol = (tid & 31) << 2;

    float acc[8][8];
    #pragma unroll
    for (int i = 0; i < 8; i++)
        #pragma unroll
        for (int j = 0; j < 8; j++) acc[i][j] = 0.f;

    for (int k0 = 0; k0 < K; k0 += BK) {
        #pragma unroll
        for (int i = 0; i < 2; i++) {
            int r = arow + i * 64;
            const float4 av = *(const float4*)(A + (size_t)(m0 + r) * lda + (k0 + acol));
            As[acol + 0][r] = av.x; As[acol + 1][r] = av.y;
            As[acol + 2][r] = av.z; As[acol + 3][r] = av.w;
        }
        #pragma unroll
        for (int i = 0; i < 2; i++) {
            int r = brow + i * 8;
            float4 bv = make_float4(0.f, 0.f, 0.f, 0.f);
            if (n0 + bcol < N)
                bv = *(const float4*)(B + (size_t)(k0 + r) * N + (n0 + bcol));
            *(float4*)&Bs[r][bcol] = bv;
        }
        __syncthreads();
        #pragma unroll
        for (int kk = 0; kk < BK; kk++) {
            float a[8], b[8];
            *(float4*)&a[0] = *(const float4*)&As[kk][ty * 8];
            *(float4*)&a[4] = *(const float4*)&As[kk][ty * 8 + 4];
            *(float4*)&b[0] = *(const float4*)&Bs[kk][tx * 8];
            *(float4*)&b[4] = *(const float4*)&Bs[kk][tx * 8 + 4];
            #pragma unroll
            for (int i = 0; i < 8; i++)
                #pragma unroll
                for (int j = 0; j < 8; j++)
                    acc[i][j] = fmaf(a[i], b[j], acc[i][j]);
        }
        __syncthreads();
    }

    #pragma unroll
    for (int i = 0; i < 8; i++) {
        int m = m0 + ty * 8 + i;
        #pragma unroll
        for (int j = 0; j < 8; j++) {
            int n = n0 + tx * 8 + j;
            if (n < N) {
                float v = acc[i][j];
                float o;
                if (EPI == 1) o = tanhf(v);
                else          o = expf(-expf(e2[n] + v));
                C[(size_t)m * N + n] = o;
            }
        }
    }
}

// ---------------- pipelined tf32 tensor-core GEMM ----------------
// C[M,N] = epi(A[M,K] @ B[K,N]); M%128==0, N%128==0, K%16==0.
// EPI: 0 none, 2 silu.  4-stage cp.async pipeline, BK=16.
#define TC_STAGES 4
#define TC_ALD 20      // As row pitch (floats)
#define TC_BLD 132     // Bs row pitch (floats)
#define TC_SMEM_FLOATS (TC_STAGES * (128 * TC_ALD + 16 * TC_BLD))

template<int EPI>
__global__ __launch_bounds__(256) void tc_gemm(
    const float* __restrict__ A,
    const float* __restrict__ B,
    float* __restrict__ C,
    int M, int N, int K)
{
    extern __shared__ float smp[];
    float* As = smp;                          // [S][128][20]
    float* Bs = smp + TC_STAGES * 128 * TC_ALD; // [S][16][132]

    int tid = threadIdx.x;
    int wid = tid >> 5;
    int lane = tid & 31;
    int wm = wid >> 2;        // 0..1
    int wn = wid & 3;         // 0..3
    int m0 = blockIdx.y * 128;
    int n0 = blockIdx.x * 128;

    // per-thread load coords (2 chunks of 16B each for A and B per stage)
    int a_r0 = tid >> 1;                 // chunk tid: row = c>>2 with c = tid + i*256
    (void)a_r0;

    wmma::fragment<wmma::accumulator, 16, 16, 8, float> acc[4][2];
    #pragma unroll
    for (int i = 0; i < 4; i++)
        #pragma unroll
        for (int j = 0; j < 2; j++) wmma::fill_fragment(acc[i][j], 0.f);

    const int KT = K >> 4;   // BK=16

    auto load_tile = [&](int t, int s) {
        int k0 = t << 4;
        #pragma unroll
        for (int i = 0; i < 2; i++) {
            int c = tid + i * 256;
            int row = c >> 2;
            int kc  = (c & 3) << 2;
            uint32_t dst = (uint32_t)__cvta_generic_to_shared(
                As + ((size_t)(s * 128 + row)) * TC_ALD + kc);
            cp_async16(dst, A + (size_t)(m0 + row) * K + (k0 + kc));
        }
        #pragma unroll
        for (int i = 0; i < 2; i++) {
            int c = tid + i * 256;
            int kr = c >> 5;
            int nc = (c & 31) << 2;
            uint32_t dst = (uint32_t)__cvta_generic_to_shared(
                Bs + ((size_t)(s * 16 + kr)) * TC_BLD + nc);
            cp_async16(dst, B + (size_t)(k0 + kr) * N + (n0 + nc));
        }
    };

    #pragma unroll
    for (int p = 0; p < TC_STAGES - 1; ++p) {
        load_tile(p, p);
        cp_commit();
    }

    for (int t = 0; t < KT; ++t) {
        int s = t & (TC_STAGES - 1);
        cp_wait<TC_STAGES - 2>();
        __syncthreads();
        int pt = t + TC_STAGES - 1;
        if (pt < KT) load_tile(pt, pt & (TC_STAGES - 1));
        cp_commit();

        #pragma unroll
        for (int kk = 0; kk < 16; kk += 8) {
            wmma::fragment<wmma::matrix_a, 16, 16, 8, wmma::precision::tf32, wmma::row_major> af[4];
            wmma::fragment<wmma::matrix_b, 16, 16, 8, wmma::precision::tf32, wmma::row_major> bf[2];
            #pragma unroll
            for (int i = 0; i < 4; i++) {
                wmma::load_matrix_sync(af[i], As + ((size_t)(s * 128 + wm * 64 + i * 16)) * TC_ALD + kk, TC_ALD);
                #pragma unroll
                for (int q = 0; q < af[i].num_elements; q++)
                    af[i].x[q] = wmma::__float_to_tf32(af[i].x[q]);
            }
            #pragma unroll
            for (int j = 0; j < 2; j++) {
                wmma::load_matrix_sync(bf[j], Bs + ((size_t)(s * 16 + kk)) * TC_BLD + wn * 32 + j * 16, TC_BLD);
                #pragma unroll
                for (int q = 0; q < bf[j].num_elements; q++)
                    bf[j].x[q] = wmma::__float_to_tf32(bf[j].x[q]);
            }
            #pragma unroll
            for (int i = 0; i < 4; i++)
                #pragma unroll
                for (int j = 0; j < 2; j++)
                    wmma::mma_sync(acc[i][j], af[i], bf[j], acc[i][j]);
        }
    }
    cp_wait<0>();
    __syncthreads();   // before smem reuse in silu epilogue

    float* stg = smp + wid * 16 * 20;   // per-warp staging (reuses As region)

    #pragma unroll
    for (int i = 0; i < 4; i++) {
        #pragma unroll
        for (int j = 0; j < 2; j++) {
            int mb = m0 + wm * 64 + i * 16;
            int nb = n0 + wn * 32 + j * 16;
            if (EPI == 0) {
                wmma::store_matrix_sync(C + (size_t)mb * N + nb, acc[i][j], N, wmma::mem_row_major);
            } else {
                wmma::store_matrix_sync(stg, acc[i][j], 20, wmma::mem_row_major);
                __syncwarp();
                int r  = lane >> 1;
                int c0 = (lane & 1) * 8;
                #pragma unroll
                for (int q = 0; q < 8; q++) {
                    float v = stg[r * 20 + c0 + q];
                    float o = v / (1.f + expf(-v));
                    C[(size_t)(mb + r) * N + (nb + c0 + q)] = o;
                }
                __syncwarp();
            }
        }
    }
}

// ---------------- fused mix: 5 outputs in one pass ----------------
// out_f = x + sx * (maa_f[n] + M1[:, f*32:+32] @ tm_w2[f])
__global__ __launch_bounds__(256) void mix_fused(
    const float* __restrict__ M1,   // [NTOK,160]
    const float* __restrict__ W2,   // [5,32,C]
    const float* __restrict__ x, const float* __restrict__ SX,
    const float* __restrict__ wmaa, const float* __restrict__ kmaa,
    const float* __restrict__ vmaa, const float* __restrict__ rmaa,
    const float* __restrict__ gmaa,
    float* __restrict__ WX, float* __restrict__ KX, float* __restrict__ VX,
    float* __restrict__ RX, float* __restrict__ GX)
{
    __shared__ float M1s[64][33];
    __shared__ float W2s[32][68];
    int tid = threadIdx.x;
    int m0 = blockIdx.y * 64, n0 = blockIdx.x * 64;
    int tx = tid & 15, ty = tid >> 4;

    // preload x, sx 4x4 tiles
    float4 xr[4], sxr[4];
    #pragma unroll
    for (int i = 0; i < 4; i++) {
        size_t idx = (size_t)(m0 + ty * 4 + i) * C_ + n0 + tx * 4;
        xr[i]  = *(const float4*)(x + idx);
        sxr[i] = *(const float4*)(SX + idx);
    }

    const float* maap[5] = {wmaa, kmaa, vmaa, rmaa, gmaa};
    float* outp[5] = {WX, KX, VX, RX, GX};

    for (int f = 0; f < 5; f++) {
        // load M1 slab [64 x 32]
        #pragma unroll
        for (int i = 0; i < 2; i++) {
            int c = tid + i * 256;
            int r = c >> 3, cc = (c & 7) << 2;
            float4 v4 = *(const float4*)(M1 + (size_t)(m0 + r) * 160 + f * 32 + cc);
            M1s[r][cc] = v4.x; M1s[r][cc + 1] = v4.y; M1s[r][cc + 2] = v4.z; M1s[r][cc + 3] = v4.w;
        }
        // load W2 slab [32 x 64]
        #pragma unroll
        for (int i = 0; i < 2; i++) {
            int c = tid + i * 256;
            int r = c >> 4, cc = (c & 15) << 2;
            float4 v4 = *(const float4*)(W2 + (size_t)(f * 32 + r) * C_ + n0 + cc);
            W2s[r][cc] = v4.x; W2s[r][cc + 1] = v4.y; W2s[r][cc + 2] = v4.z; W2s[r][cc + 3] = v4.w;
        }
        __syncthreads();

        float acc[4][4];
        #pragma unroll
        for (int i = 0; i < 4; i++)
            #pragma unroll
            for (int j = 0; j < 4; j++) acc[i][j] = 0.f;

        #pragma unroll
        for (int k = 0; k < 32; k++) {
            float a[4], b[4];
            #pragma unroll
            for (int i = 0; i < 4; i++) a[i] = M1s[ty * 4 + i][k];
            #pragma unroll
            for (int j = 0; j < 4; j++) b[j] = W2s[k][tx * 4 + j];
            #pragma unroll
            for (int i = 0; i < 4; i++)
                #pragma unroll
                for (int j = 0; j < 4; j++)
                    acc[i][j] = fmaf(a[i], b[j], acc[i][j]);
        }

        float4 mv = *(const float4*)(maap[f] + n0 + tx * 4);
        float* op = outp[f];
        #pragma unroll
        for (int i = 0; i < 4; i++) {
            size_t idx = (size_t)(m0 + ty * 4 + i) * C_ + n0 + tx * 4;
            float4 o;
            const float* xi = (const float*)&xr[i];
            const float* si = (const float*)&sxr[i];
            const float* mi = (const float*)&mv;
            float* oo = (float*)&o;
            #pragma unroll
            for (int j = 0; j < 4; j++)
                oo[j] = fmaf(si[j], mi[j] + acc[i][j], xi[j]);
            *(float4*)(op + idx) = o;
        }
        __syncthreads();
    }
}

// ---------------- WKV scan, v-split across 2 blocks per (b,h) ----------------
// grid 128: idx -> b (>>5), h ((>>1)&15), half (&1). 128 threads: kq=tid>>5, v=tid&31.
__global__ __launch_bounds__(128) void scan_kernel2(
    const float* __restrict__ R, const float* __restrict__ Kt,
    const float* __restrict__ V, const float* __restrict__ W,
    const float* __restrict__ u,
    float* __restrict__ Y)
{
    int idx = blockIdx.x;
    int b = idx >> 5, h = (idx >> 1) & 15, half = idx & 1;
    int tid = threadIdx.x;
    int v = tid & 31, kq = tid >> 5;

    __shared__ float r_s[64], k_s[64], w_s[64], v_s[32], u_s[64];
    __shared__ float red[128];

    if (tid < 64) u_s[tid] = u[h * 64 + tid];

    float state[16];
    #pragma unroll
    for (int i = 0; i < 16; i++) state[i] = 0.f;

    const size_t base = (size_t)b * T_ * C_ + (size_t)h * 64;
    const int vbase = half * 32;

    // prefetch t=0 (two values per thread)
    float pa, pb = 0.f;
    {
        if (tid < 64) { pa = R[base + tid]; pb = W[base + tid]; }
        else {
            int c = tid - 64;
            pa = Kt[base + c];
            if (c < 32) pb = V[base + vbase + c];
        }
    }

    for (int t = 0; t < T_; ++t) {
        if (tid < 64) { r_s[tid] = pa; w_s[tid] = pb; }
        else {
            int c = tid - 64;
            k_s[c] = pa;
            if (c < 32) v_s[c] = pb;
        }
        __syncthreads();   // bar A

        if (t < T_ - 1) {
            size_t nb = base + (size_t)(t + 1) * C_;
            if (tid < 64) { pa = R[nb + tid]; pb = W[nb + tid]; }
            else {
                int c = tid - 64;
                pa = Kt[nb + c];
                if (c < 32) pb = V[nb + vbase + c];
            }
        }

        float vv = v_s[v];
        float y = 0.f;
        #pragma unroll
        for (int i = 0; i < 16; i++) {
            int kk = kq * 16 + i;
            float a = k_s[kk] * vv;
            y = fmaf(r_s[kk], fmaf(u_s[kk], a, state[i]), y);
            state[i] = fmaf(w_s[kk], state[i], a);
        }
        red[tid] = y;
        __syncthreads();   // bar B

        if (kq == 0) {
            float yd = ((red[v] + red[32 + v]) + (red[64 + v] + red[96 + v])) * 0.125f;
            Y[base + (size_t)t * C_ + vbase + v] = yd;
        }
        // kq==0 reads of red complete before it reaches bar A of t+1;
        // other threads only overwrite red after that barrier.
    }
}

// ---------------- groupnorm + ln affine + gate (in-place on Y) ----------------
__global__ __launch_bounds__(256) void norm_gate(
    float* __restrict__ Y, const float* __restrict__ G,
    const float* __restrict__ lnw, const float* __restrict__ lnb)
{
    int wid = threadIdx.x >> 5;
    int lane = threadIdx.x & 31;
    int gi = blockIdx.x * 8 + wid;          // group = token*16 + head
    int m = gi >> 4, h = gi & 15;
    size_t p = (size_t)m * C_ + h * 64;

    float a = Y[p + lane], b2 = Y[p + 32 + lane];
    float s1 = a + b2;
    float s2 = a * a + b2 * b2;
    #pragma unroll
    for (int o = 16; o > 0; o >>= 1) {
        s1 += __shfl_xor_sync(0xffffffffu, s1, o);
        s2 += __shfl_xor_sync(0xffffffffu, s2, o);
    }
    float mean = s1 * (1.f / 64.f);
    float var  = s2 * (1.f / 64.f) - mean * mean;
    float rs = rsqrtf(var + 1e-5f);

    int c0 = h * 64 + lane;
    float o1 = fmaf((a  - mean) * rs, lnw[c0],      lnb[c0])      * G[p + lane];
    float o2 = fmaf((b2 - mean) * rs, lnw[c0 + 32], lnb[c0 + 32]) * G[p + 32 + lane];
    Y[p + lane] = o1;
    Y[p + 32 + lane] = o2;
}

// ---------------- launch ----------------
extern "C" void kernel_launch(void* const* d_in, const int* in_sizes, int n_in,
                              void* d_out, int out_size)
{
    (void)in_sizes; (void)n_in; (void)out_size;
    const float* x          = (const float*)d_in[0];
    const float* x_maa      = (const float*)d_in[1];
    const float* w_maa      = (const float*)d_in[2];
    const float* k_maa      = (const float*)d_in[3];
    const float* v_maa      = (const float*)d_in[4];
    const float* r_maa      = (const float*)d_in[5];
    const float* g_maa      = (const float*)d_in[6];
    const float* tm_w1      = (const float*)d_in[7];
    const float* tm_w2      = (const float*)d_in[8];
    const float* td_w1      = (const float*)d_in[9];
    const float* td_w2      = (const float*)d_in[10];
    const float* time_decay = (const float*)d_in[11];
    const float* time_first = (const float*)d_in[12];
    const float* Wr         = (const float*)d_in[13];
    const float* Wk         = (const float*)d_in[14];
    const float* Wv         = (const float*)d_in[15];
    const float* Wg         = (const float*)d_in[16];
    const float* Wo         = (const float*)d_in[17];
    const float* ln_w       = (const float*)d_in[18];
    const float* ln_b       = (const float*)d_in[19];
    float* out = (float*)d_out;

    float *SX, *XS, *M1, *WX, *KX, *VX, *RX, *GX, *Rb, *Kb, *Vb, *Gb, *Wd, *WT, *Yb;
    cudaGetSymbolAddress((void**)&SX, d_SX);
    cudaGetSymbolAddress((void**)&XS, d_XS);
    cudaGetSymbolAddress((void**)&M1, d_M1);
    cudaGetSymbolAddress((void**)&WX, d_WX);
    cudaGetSymbolAddress((void**)&KX, d_KX);
    cudaGetSymbolAddress((void**)&VX, d_VX);
    cudaGetSymbolAddress((void**)&RX, d_RX);
    cudaGetSymbolAddress((void**)&GX, d_GX);
    cudaGetSymbolAddress((void**)&Rb, d_R);
    cudaGetSymbolAddress((void**)&Kb, d_K);
    cudaGetSymbolAddress((void**)&Vb, d_V);
    cudaGetSymbolAddress((void**)&Gb, d_G);
    cudaGetSymbolAddress((void**)&Wd, d_Wd);
    cudaGetSymbolAddress((void**)&WT, d_WT);
    cudaGetSymbolAddress((void**)&Yb, d_Y);

    const int tc_smem = TC_SMEM_FLOATS * (int)sizeof(float);
    cudaFuncSetAttribute(tc_gemm<0>, cudaFuncAttributeMaxDynamicSharedMemorySize, tc_smem);
    cudaFuncSetAttribute(tc_gemm<2>, cudaFuncAttributeMaxDynamicSharedMemorySize, tc_smem);

    dim3 blk(256);

    // 1. prep
    prep_kernel<<<(NTOK * C_ / 4 + 255) / 256, blk>>>(x, x_maa, SX, XS);

    // 2. M1 = tanh(XS @ tm_w1)   [4096,160]
    gemm_kernel<1><<<dim3(2, 32), blk>>>(XS, C_, tm_w1, M1, NTOK, 160, C_, nullptr);

    // 3. fused mix -> WX,KX,VX,RX,GX
    mix_fused<<<dim3(16, 64), blk>>>(M1, tm_w2, x, SX,
                                     w_maa, k_maa, v_maa, r_maa, g_maa,
                                     WX, KX, VX, RX, GX);

    // 4. projections (pipelined tf32 tensor core)
    tc_gemm<0><<<dim3(8, 32), blk, tc_smem>>>(RX, Wr, Rb, NTOK, C_, C_);
    tc_gemm<0><<<dim3(8, 32), blk, tc_smem>>>(KX, Wk, Kb, NTOK, C_, C_);
    tc_gemm<0><<<dim3(8, 32), blk, tc_smem>>>(VX, Wv, Vb, NTOK, C_, C_);
    tc_gemm<2><<<dim3(8, 32), blk, tc_smem>>>(GX, Wg, Gb, NTOK, C_, C_);

    // 5. decay LoRA: WT = tanh(WX @ td_w1); Wd = exp(-exp(time_decay + WT @ td_w2))
    gemm_kernel<1><<<dim3(1, 32), blk>>>(WX, C_, td_w1, WT, NTOK, 64, C_, nullptr);
    gemm_kernel<4><<<dim3(8, 32), blk>>>(WT, 64, td_w2, Wd, NTOK, C_, 64, time_decay);

    // 6. WKV scan (v-split) then groupnorm+gate
    scan_kernel2<<<128, 128>>>(Rb, Kb, Vb, Wd, time_first, Yb);
    norm_gate<<<NTOK * H_ / 8, blk>>>(Yb, Gb, ln_w, ln_b);

    // 7. output projection
    tc_gemm<0><<<dim3(8, 32), blk, tc_smem>>>(Yb, Wo, out, NTOK, C_, C_);
}

// round 6
// speedup vs baseline: 1.4971x; 1.1678x over previous
#include <cuda_runtime.h>
#include <mma.h>
#include <math.h>
#include <stdint.h>

using namespace nvcuda;

#define B_ 4
#define T_ 1024
#define C_ 1024
#define H_ 16
#define NTOK (B_*T_)
#define KS_ 4   // split-K factor for skinny GEMMs

// ---------------- scratch (device globals; no allocation allowed) ----------------
__device__ float d_SX[NTOK*C_];
__device__ float d_XS[NTOK*C_];
__device__ float d_M1[NTOK*160];
__device__ float d_WX[NTOK*C_];
__device__ float d_KX[NTOK*C_];
__device__ float d_VX[NTOK*C_];
__device__ float d_RX[NTOK*C_];
__device__ float d_GX[NTOK*C_];
__device__ float d_R [NTOK*C_];
__device__ float d_K [NTOK*C_];
__device__ float d_V [NTOK*C_];
__device__ float d_G [NTOK*C_];
__device__ float d_Wd[NTOK*C_];
__device__ float d_WT[NTOK*64];
__device__ float d_Y [NTOK*C_];
__device__ float d_Wrnd[5*C_*C_];        // 5 tf32-rounded weights [K,N]
__device__ float d_P1[KS_*NTOK*160];     // split-K partials (tm)
__device__ float d_P2[KS_*NTOK*64];      // split-K partials (td)

// ---------------- helpers ----------------
__device__ __forceinline__ void cp_async16(uint32_t dst, const void* src) {
    asm volatile("cp.async.cg.shared.global [%0], [%1], 16;\n" :: "r"(dst), "l"(src));
}
__device__ __forceinline__ void cp_commit() { asm volatile("cp.async.commit_group;\n"); }
template<int N> __device__ __forceinline__ void cp_wait() {
    asm volatile("cp.async.wait_group %0;\n" :: "n"(N));
}
__device__ __forceinline__ float to_tf32(float x) {
    uint32_t r;
    asm("cvt.rna.tf32.f32 %0, %1;" : "=r"(r) : "f"(x));   // tf32 cvt needs .b32 dst
    return __uint_as_float(r);
}

// ---------------- prep: sx = shift(x) - x ; xs = x + sx * x_maa ----------------
__global__ void prep_kernel(const float* __restrict__ x, const float* __restrict__ xmaa,
                            float* __restrict__ SX, float* __restrict__ XS)
{
    int i4 = blockIdx.x * blockDim.x + threadIdx.x;
    int i  = i4 * 4;
    if (i >= NTOK * C_) return;
    int m = i >> 10;
    int c = i & 1023;
    int t = m & (T_ - 1);
    float4 xv = *(const float4*)(x + i);
    float4 xp = make_float4(0.f, 0.f, 0.f, 0.f);
    if (t != 0) xp = *(const float4*)(x + i - C_);
    float4 ma = *(const float4*)(xmaa + c);
    float4 sx, xs;
    sx.x = xp.x - xv.x; sx.y = xp.y - xv.y; sx.z = xp.z - xv.z; sx.w = xp.w - xv.w;
    xs.x = fmaf(sx.x, ma.x, xv.x); xs.y = fmaf(sx.y, ma.y, xv.y);
    xs.z = fmaf(sx.z, ma.z, xv.z); xs.w = fmaf(sx.w, ma.w, xv.w);
    *(float4*)(SX + i) = sx;
    *(float4*)(XS + i) = xs;
}

// ---------------- round 5 weights to tf32 (layout preserved [K,N]) ----------------
__global__ void round5(const float* __restrict__ W0, const float* __restrict__ W1,
                       const float* __restrict__ W2, const float* __restrict__ W3,
                       const float* __restrict__ W4, float* __restrict__ out)
{
    const float* srcs[5] = {W0, W1, W2, W3, W4};
    int i = (blockIdx.x * blockDim.x + threadIdx.x) * 4;
    int which = blockIdx.y;
    const float* src = srcs[which];
    float* dst = out + (size_t)which * C_ * C_;
    float4 v = *(const float4*)(src + i);
    v.x = to_tf32(v.x); v.y = to_tf32(v.y); v.z = to_tf32(v.z); v.w = to_tf32(v.w);
    *(float4*)(dst + i) = v;
}

// ---------------- split-K fp32 GEMM for skinny N ----------------
// P[z][M][N] partial = A[M, kslice] @ B[kslice, N];  grid (ceil(N/64), M/128, KS)
__global__ __launch_bounds__(256) void splitk_gemm(
    const float* __restrict__ A, int lda,
    const float* __restrict__ B,
    float* __restrict__ P,
    int M, int N, int K)
{
    const int BM = 128, BN = 64, BK = 16;
    __shared__ float As[BK][BM + 4];
    __shared__ float Bs[BK][BN + 4];
    int tid = threadIdx.x;
    int n0 = blockIdx.x * BN;
    int m0 = blockIdx.y * BM;
    int KC = K / gridDim.z;
    int kbeg = blockIdx.z * KC;

    int arow = tid >> 2;           // 0..63
    int acol = (tid & 3) << 2;
    int brow = tid >> 4;           // 0..15
    int bcol = (tid & 15) << 2;    // 0..60
    int tx = tid & 15, ty = tid >> 4;

    float acc[8][4];
    #pragma unroll
    for (int i = 0; i < 8; i++)
        #pragma unroll
        for (int j = 0; j < 4; j++) acc[i][j] = 0.f;

    for (int k0 = kbeg; k0 < kbeg + KC; k0 += BK) {
        #pragma unroll
        for (int i = 0; i < 2; i++) {
            int r = arow + i * 64;
            const float4 av = *(const float4*)(A + (size_t)(m0 + r) * lda + (k0 + acol));
            As[acol + 0][r] = av.x; As[acol + 1][r] = av.y;
            As[acol + 2][r] = av.z; As[acol + 3][r] = av.w;
        }
        {
            float4 bv = make_float4(0.f, 0.f, 0.f, 0.f);
            if (n0 + bcol < N)
                bv = *(const float4*)(B + (size_t)(k0 + brow) * N + (n0 + bcol));
            *(float4*)&Bs[brow][bcol] = bv;
        }
        __syncthreads();
        #pragma unroll
        for (int kk = 0; kk < BK; kk++) {
            float a[8], b[4];
            *(float4*)&a[0] = *(const float4*)&As[kk][ty * 8];
            *(float4*)&a[4] = *(const float4*)&As[kk][ty * 8 + 4];
            *(float4*)&b[0] = *(const float4*)&Bs[kk][tx * 4];
            #pragma unroll
            for (int i = 0; i < 8; i++)
                #pragma unroll
                for (int j = 0; j < 4; j++)
                    acc[i][j] = fmaf(a[i], b[j], acc[i][j]);
        }
        __syncthreads();
    }

    float* Pz = P + (size_t)blockIdx.z * M * N;
    #pragma unroll
    for (int i = 0; i < 8; i++) {
        int m = m0 + ty * 8 + i;
        int n = n0 + tx * 4;
        if (n < N)
            *(float4*)(Pz + (size_t)m * N + n) = *(float4*)&acc[i][0];
    }
}

// ---------------- reduce split-K partials + tanh ----------------
__global__ void reduce_tanh(const float* __restrict__ P, float* __restrict__ out, int MN)
{
    int i = blockIdx.x * blockDim.x + threadIdx.x;
    if (i >= MN) return;
    float s = 0.f;
    #pragma unroll
    for (int z = 0; z < KS_; z++) s += P[(size_t)z * MN + i];
    out[i] = tanhf(s);
}

// ---------------- fp32 GEMM with decay epilogue (K=64) ----------------
// Wd = exp(-exp(e2[n] + WT @ td_w2))
__global__ __launch_bounds__(256) void gemm_decay(
    const float* __restrict__ A, int lda,
    const float* __restrict__ B,
    float* __restrict__ C,
    int M, int N, int K,
    const float* __restrict__ e2)
{
    const int BM = 128, BN = 128, BK = 16;
    __shared__ float As[BK][BM + 4];
    __shared__ float Bs[BK][BN + 4];
    int tid = threadIdx.x;
    int m0 = blockIdx.y * BM;
    int n0 = blockIdx.x * BN;
    int tx = tid & 15, ty = tid >> 4;

    int arow = tid >> 2;
    int acol = (tid & 3) << 2;
    int brow = tid >> 5;
    int bcol = (tid & 31) << 2;

    float acc[8][8];
    #pragma unroll
    for (int i = 0; i < 8; i++)
        #pragma unroll
        for (int j = 0; j < 8; j++) acc[i][j] = 0.f;

    for (int k0 = 0; k0 < K; k0 += BK) {
        #pragma unroll
        for (int i = 0; i < 2; i++) {
            int r = arow + i * 64;
            const float4 av = *(const float4*)(A + (size_t)(m0 + r) * lda + (k0 + acol));
            As[acol + 0][r] = av.x; As[acol + 1][r] = av.y;
            As[acol + 2][r] = av.z; As[acol + 3][r] = av.w;
        }
        #pragma unroll
        for (int i = 0; i < 2; i++) {
            int r = brow + i * 8;
            float4 bv = *(const float4*)(B + (size_t)(k0 + r) * N + (n0 + bcol));
            *(float4*)&Bs[r][bcol] = bv;
        }
        __syncthreads();
        #pragma unroll
        for (int kk = 0; kk < BK; kk++) {
            float a[8], b[8];
            *(float4*)&a[0] = *(const float4*)&As[kk][ty * 8];
            *(float4*)&a[4] = *(const float4*)&As[kk][ty * 8 + 4];
            *(float4*)&b[0] = *(const float4*)&Bs[kk][tx * 8];
            *(float4*)&b[4] = *(const float4*)&Bs[kk][tx * 8 + 4];
            #pragma unroll
            for (int i = 0; i < 8; i++)
                #pragma unroll
                for (int j = 0; j < 8; j++)
                    acc[i][j] = fmaf(a[i], b[j], acc[i][j]);
        }
        __syncthreads();
    }

    #pragma unroll
    for (int i = 0; i < 8; i++) {
        int m = m0 + ty * 8 + i;
        #pragma unroll
        for (int j = 0; j < 8; j++) {
            int n = n0 + tx * 8 + j;
            C[(size_t)m * N + n] = expf(-expf(e2[n] + acc[i][j]));
        }
    }
}

// ---------------- pipelined tf32 wmma GEMM (pre-rounded inputs) ----------------
// C[M,N] = epi(A[M,K] @ B[K,N]); M%128==0, N%128==0, K%16==0.
// EPI: 0 none, 2 silu.  3-stage cp.async pipeline, BK=16, 2 CTAs/SM.
#define TC_STAGES 3
#define TC_ALD 20
#define TC_BLD 132
#define TC_SMEM_FLOATS (TC_STAGES * (128 * TC_ALD + 16 * TC_BLD))

template<int EPI>
__global__ __launch_bounds__(256, 2) void tc_gemm(
    const float* __restrict__ A,
    const float* __restrict__ B,
    float* __restrict__ C,
    int M, int N, int K)
{
    extern __shared__ float smp[];
    float* As = smp;                             // [S][128][20]
    float* Bs = smp + TC_STAGES * 128 * TC_ALD;  // [S][16][132]

    int tid = threadIdx.x;
    int wid = tid >> 5;
    int lane = tid & 31;
    int wm = wid >> 2;        // 0..1
    int wn = wid & 3;         // 0..3
    int m0 = blockIdx.y * 128;
    int n0 = blockIdx.x * 128;

    wmma::fragment<wmma::accumulator, 16, 16, 8, float> acc[4][2];
    #pragma unroll
    for (int i = 0; i < 4; i++)
        #pragma unroll
        for (int j = 0; j < 2; j++) wmma::fill_fragment(acc[i][j], 0.f);

    const int KT = K >> 4;

    auto load_tile = [&](int t, int s) {
        int k0 = t << 4;
        #pragma unroll
        for (int i = 0; i < 2; i++) {
            int c = tid + i * 256;
            int row = c >> 2;
            int kc  = (c & 3) << 2;
            uint32_t dst = (uint32_t)__cvta_generic_to_shared(
                As + ((size_t)(s * 128 + row)) * TC_ALD + kc);
            cp_async16(dst, A + (size_t)(m0 + row) * K + (k0 + kc));
        }
        #pragma unroll
        for (int i = 0; i < 2; i++) {
            int c = tid + i * 256;
            int kr = c >> 5;
            int nc = (c & 31) << 2;
            uint32_t dst = (uint32_t)__cvta_generic_to_shared(
                Bs + ((size_t)(s * 16 + kr)) * TC_BLD + nc);
            cp_async16(dst, B + (size_t)(k0 + kr) * N + (n0 + nc));
        }
    };

    load_tile(0, 0); cp_commit();
    load_tile(1, 1); cp_commit();

    for (int t = 0; t < KT; ++t) {
        int s = t % TC_STAGES;
        cp_wait<TC_STAGES - 2>();
        __syncthreads();
        int pt = t + TC_STAGES - 1;
        if (pt < KT) load_tile(pt, pt % TC_STAGES);
        cp_commit();

        #pragma unroll
        for (int kk = 0; kk < 16; kk += 8) {
            wmma::fragment<wmma::matrix_a, 16, 16, 8, wmma::precision::tf32, wmma::row_major> af[4];
            wmma::fragment<wmma::matrix_b, 16, 16, 8, wmma::precision::tf32, wmma::row_major> bf[2];
            #pragma unroll
            for (int i = 0; i < 4; i++)
                wmma::load_matrix_sync(af[i], As + ((size_t)(s * 128 + wm * 64 + i * 16)) * TC_ALD + kk, TC_ALD);
            #pragma unroll
            for (int j = 0; j < 2; j++)
                wmma::load_matrix_sync(bf[j], Bs + ((size_t)(s * 16 + kk)) * TC_BLD + wn * 32 + j * 16, TC_BLD);
            // inputs pre-rounded to tf32 -> no per-element cvt needed
            #pragma unroll
            for (int i = 0; i < 4; i++)
                #pragma unroll
                for (int j = 0; j < 2; j++)
                    wmma::mma_sync(acc[i][j], af[i], bf[j], acc[i][j]);
        }
    }
    cp_wait<0>();
    __syncthreads();

    float* stg = smp + wid * 16 * 20;

    #pragma unroll
    for (int i = 0; i < 4; i++) {
        #pragma unroll
        for (int j = 0; j < 2; j++) {
            int mb = m0 + wm * 64 + i * 16;
            int nb = n0 + wn * 32 + j * 16;
            if (EPI == 0) {
                wmma::store_matrix_sync(C + (size_t)mb * N + nb, acc[i][j], N, wmma::mem_row_major);
            } else {
                wmma::store_matrix_sync(stg, acc[i][j], 20, wmma::mem_row_major);
                __syncwarp();
                int r  = lane >> 1;
                int c0 = (lane & 1) * 8;
                #pragma unroll
                for (int q = 0; q < 8; q++) {
                    float v = stg[r * 20 + c0 + q];
                    float o = v / (1.f + expf(-v));
                    C[(size_t)(mb + r) * N + (nb + c0 + q)] = o;
                }
                __syncwarp();
            }
        }
    }
}

// ---------------- fused mix: 5 outputs in one pass ----------------
// out_f = x + sx * (maa_f[n] + M1[:, f*32:+32] @ tm_w2[f]); f>=1 rounded to tf32
__global__ __launch_bounds__(256) void mix_fused(
    const float* __restrict__ M1,
    const float* __restrict__ W2,
    const float* __restrict__ x, const float* __restrict__ SX,
    const float* __restrict__ wmaa, const float* __restrict__ kmaa,
    const float* __restrict__ vmaa, const float* __restrict__ rmaa,
    const float* __restrict__ gmaa,
    float* __restrict__ WX, float* __restrict__ KX, float* __restrict__ VX,
    float* __restrict__ RX, float* __restrict__ GX)
{
    __shared__ float M1s[64][33];
    __shared__ float W2s[32][68];
    int tid = threadIdx.x;
    int m0 = blockIdx.y * 64, n0 = blockIdx.x * 64;
    int tx = tid & 15, ty = tid >> 4;

    float4 xr[4], sxr[4];
    #pragma unroll
    for (int i = 0; i < 4; i++) {
        size_t idx = (size_t)(m0 + ty * 4 + i) * C_ + n0 + tx * 4;
        xr[i]  = *(const float4*)(x + idx);
        sxr[i] = *(const float4*)(SX + idx);
    }

    const float* maap[5] = {wmaa, kmaa, vmaa, rmaa, gmaa};
    float* outp[5] = {WX, KX, VX, RX, GX};

    for (int f = 0; f < 5; f++) {
        #pragma unroll
        for (int i = 0; i < 2; i++) {
            int c = tid + i * 256;
            int r = c >> 3, cc = (c & 7) << 2;
            float4 v4 = *(const float4*)(M1 + (size_t)(m0 + r) * 160 + f * 32 + cc);
            M1s[r][cc] = v4.x; M1s[r][cc + 1] = v4.y; M1s[r][cc + 2] = v4.z; M1s[r][cc + 3] = v4.w;
        }
        #pragma unroll
        for (int i = 0; i < 2; i++) {
            int c = tid + i * 256;
            int r = c >> 4, cc = (c & 15) << 2;
            float4 v4 = *(const float4*)(W2 + (size_t)(f * 32 + r) * C_ + n0 + cc);
            W2s[r][cc] = v4.x; W2s[r][cc + 1] = v4.y; W2s[r][cc + 2] = v4.z; W2s[r][cc + 3] = v4.w;
        }
        __syncthreads();

        float acc[4][4];
        #pragma unroll
        for (int i = 0; i < 4; i++)
            #pragma unroll
            for (int j = 0; j < 4; j++) acc[i][j] = 0.f;

        #pragma unroll
        for (int k = 0; k < 32; k++) {
            float a[4], b[4];
            #pragma unroll
            for (int i = 0; i < 4; i++) a[i] = M1s[ty * 4 + i][k];
            #pragma unroll
            for (int j = 0; j < 4; j++) b[j] = W2s[k][tx * 4 + j];
            #pragma unroll
            for (int i = 0; i < 4; i++)
                #pragma unroll
                for (int j = 0; j < 4; j++)
                    acc[i][j] = fmaf(a[i], b[j], acc[i][j]);
        }

        float4 mv = *(const float4*)(maap[f] + n0 + tx * 4);
        float* op = outp[f];
        bool rnd = (f >= 1);   // KX,VX,RX,GX feed tf32 tensor GEMMs
        #pragma unroll
        for (int i = 0; i < 4; i++) {
            size_t idx = (size_t)(m0 + ty * 4 + i) * C_ + n0 + tx * 4;
            float4 o;
            const float* xi = (const float*)&xr[i];
            const float* si = (const float*)&sxr[i];
            const float* mi = (const float*)&mv;
            float* oo = (float*)&o;
            #pragma unroll
            for (int j = 0; j < 4; j++) {
                float v = fmaf(si[j], mi[j] + acc[i][j], xi[j]);
                oo[j] = rnd ? to_tf32(v) : v;
            }
            *(float4*)(op + idx) = o;
        }
        __syncthreads();
    }
}

// ---------------- WKV scan, v-split across 2 blocks per (b,h) ----------------
__global__ __launch_bounds__(128) void scan_kernel2(
    const float* __restrict__ R, const float* __restrict__ Kt,
    const float* __restrict__ V, const float* __restrict__ W,
    const float* __restrict__ u,
    float* __restrict__ Y)
{
    int idx = blockIdx.x;
    int b = idx >> 5, h = (idx >> 1) & 15, half = idx & 1;
    int tid = threadIdx.x;
    int v = tid & 31, kq = tid >> 5;

    __shared__ float r_s[64], k_s[64], w_s[64], v_s[32];
    __shared__ float red[128];

    float u_r[16];
    #pragma unroll
    for (int i = 0; i < 16; i++) u_r[i] = u[h * 64 + kq * 16 + i];

    float state[16];
    #pragma unroll
    for (int i = 0; i < 16; i++) state[i] = 0.f;

    const size_t base = (size_t)b * T_ * C_ + (size_t)h * 64;
    const int vbase = half * 32;

    float pa, pb = 0.f;
    {
        if (tid < 64) { pa = R[base + tid]; pb = W[base + tid]; }
        else {
            int c = tid - 64;
            pa = Kt[base + c];
            if (c < 32) pb = V[base + vbase + c];
        }
    }

    for (int t = 0; t < T_; ++t) {
        if (tid < 64) { r_s[tid] = pa; w_s[tid] = pb; }
        else {
            int c = tid - 64;
            k_s[c] = pa;
            if (c < 32) v_s[c] = pb;
        }
        __syncthreads();

        if (t < T_ - 1) {
            size_t nb = base + (size_t)(t + 1) * C_;
            if (tid < 64) { pa = R[nb + tid]; pb = W[nb + tid]; }
            else {
                int c = tid - 64;
                pa = Kt[nb + c];
                if (c < 32) pb = V[nb + vbase + c];
            }
        }

        float vv = v_s[v];
        float y = 0.f;
        #pragma unroll
        for (int i = 0; i < 16; i++) {
            int kk = kq * 16 + i;
            float a = k_s[kk] * vv;
            y = fmaf(r_s[kk], fmaf(u_r[i], a, state[i]), y);
            state[i] = fmaf(w_s[kk], state[i], a);
        }
        red[tid] = y;
        __syncthreads();

        if (kq == 0) {
            float yd = ((red[v] + red[32 + v]) + (red[64 + v] + red[96 + v])) * 0.125f;
            Y[base + (size_t)t * C_ + vbase + v] = yd;
        }
    }
}

// ---------------- groupnorm + ln affine + gate (in-place on Y, tf32-rounded) ----------------
__global__ __launch_bounds__(256) void norm_gate(
    float* __restrict__ Y, const float* __restrict__ G,
    const float* __restrict__ lnw, const float* __restrict__ lnb)
{
    int wid = threadIdx.x >> 5;
    int lane = threadIdx.x & 31;
    int gi = blockIdx.x * 8 + wid;
    int m = gi >> 4, h = gi & 15;
    size_t p = (size_t)m * C_ + h * 64;

    float a = Y[p + lane], b2 = Y[p + 32 + lane];
    float s1 = a + b2;
    float s2 = a * a + b2 * b2;
    #pragma unroll
    for (int o = 16; o > 0; o >>= 1) {
        s1 += __shfl_xor_sync(0xffffffffu, s1, o);
        s2 += __shfl_xor_sync(0xffffffffu, s2, o);
    }
    float mean = s1 * (1.f / 64.f);
    float var  = s2 * (1.f / 64.f) - mean * mean;
    float rs = rsqrtf(var + 1e-5f);

    int c0 = h * 64 + lane;
    float o1 = fmaf((a  - mean) * rs, lnw[c0],      lnb[c0])      * G[p + lane];
    float o2 = fmaf((b2 - mean) * rs, lnw[c0 + 32], lnb[c0 + 32]) * G[p + 32 + lane];
    Y[p + lane]      = to_tf32(o1);
    Y[p + 32 + lane] = to_tf32(o2);
}

// ---------------- launch ----------------
extern "C" void kernel_launch(void* const* d_in, const int* in_sizes, int n_in,
                              void* d_out, int out_size)
{
    (void)in_sizes; (void)n_in; (void)out_size;
    const float* x          = (const float*)d_in[0];
    const float* x_maa      = (const float*)d_in[1];
    const float* w_maa      = (const float*)d_in[2];
    const float* k_maa      = (const float*)d_in[3];
    const float* v_maa      = (const float*)d_in[4];
    const float* r_maa      = (const float*)d_in[5];
    const float* g_maa      = (const float*)d_in[6];
    const float* tm_w1      = (const float*)d_in[7];
    const float* tm_w2      = (const float*)d_in[8];
    const float* td_w1      = (const float*)d_in[9];
    const float* td_w2      = (const float*)d_in[10];
    const float* time_decay = (const float*)d_in[11];
    const float* time_first = (const float*)d_in[12];
    const float* Wr         = (const float*)d_in[13];
    const float* Wk         = (const float*)d_in[14];
    const float* Wv         = (const float*)d_in[15];
    const float* Wg         = (const float*)d_in[16];
    const float* Wo         = (const float*)d_in[17];
    const float* ln_w       = (const float*)d_in[18];
    const float* ln_b       = (const float*)d_in[19];
    float* out = (float*)d_out;

    float *SX, *XS, *M1, *WX, *KX, *VX, *RX, *GX, *Rb, *Kb, *Vb, *Gb, *Wd, *WT, *Yb, *Wrn, *P1, *P2;
    cudaGetSymbolAddress((void**)&SX, d_SX);
    cudaGetSymbolAddress((void**)&XS, d_XS);
    cudaGetSymbolAddress((void**)&M1, d_M1);
    cudaGetSymbolAddress((void**)&WX, d_WX);
    cudaGetSymbolAddress((void**)&KX, d_KX);
    cudaGetSymbolAddress((void**)&VX, d_VX);
    cudaGetSymbolAddress((void**)&RX, d_RX);
    cudaGetSymbolAddress((void**)&GX, d_GX);
    cudaGetSymbolAddress((void**)&Rb, d_R);
    cudaGetSymbolAddress((void**)&Kb, d_K);
    cudaGetSymbolAddress((void**)&Vb, d_V);
    cudaGetSymbolAddress((void**)&Gb, d_G);
    cudaGetSymbolAddress((void**)&Wd, d_Wd);
    cudaGetSymbolAddress((void**)&WT, d_WT);
    cudaGetSymbolAddress((void**)&Yb, d_Y);
    cudaGetSymbolAddress((void**)&Wrn, d_Wrnd);
    cudaGetSymbolAddress((void**)&P1, d_P1);
    cudaGetSymbolAddress((void**)&P2, d_P2);

    const int tc_smem = TC_SMEM_FLOATS * (int)sizeof(float);
    cudaFuncSetAttribute(tc_gemm<0>, cudaFuncAttributeMaxDynamicSharedMemorySize, tc_smem);
    cudaFuncSetAttribute(tc_gemm<2>, cudaFuncAttributeMaxDynamicSharedMemorySize, tc_smem);

    dim3 blk(256);

    // 0. tf32-round weights: order r,k,v,g,o
    round5<<<dim3(C_ * C_ / 4 / 256, 5), blk>>>(Wr, Wk, Wv, Wg, Wo, Wrn);

    // 1. prep
    prep_kernel<<<(NTOK * C_ / 4 + 255) / 256, blk>>>(x, x_maa, SX, XS);

    // 2. M1 = tanh(XS @ tm_w1)   [4096,160]  (split-K)
    splitk_gemm<<<dim3(3, 32, KS_), blk>>>(XS, C_, tm_w1, P1, NTOK, 160, C_);
    reduce_tanh<<<(NTOK * 160 + 255) / 256, blk>>>(P1, M1, NTOK * 160);

    // 3. fused mix -> WX,KX,VX,RX,GX
    mix_fused<<<dim3(16, 64), blk>>>(M1, tm_w2, x, SX,
                                     w_maa, k_maa, v_maa, r_maa, g_maa,
                                     WX, KX, VX, RX, GX);

    // 4. projections (tf32 wmma, pre-rounded)
    tc_gemm<0><<<dim3(8, 32), blk, tc_smem>>>(RX, Wrn + 0 * C_ * C_, Rb, NTOK, C_, C_);
    tc_gemm<0><<<dim3(8, 32), blk, tc_smem>>>(KX, Wrn + 1 * C_ * C_, Kb, NTOK, C_, C_);
    tc_gemm<0><<<dim3(8, 32), blk, tc_smem>>>(VX, Wrn + 2 * C_ * C_, Vb, NTOK, C_, C_);
    tc_gemm<2><<<dim3(8, 32), blk, tc_smem>>>(GX, Wrn + 3 * C_ * C_, Gb, NTOK, C_, C_);

    // 5. decay LoRA: WT = tanh(WX @ td_w1) (split-K); Wd = exp(-exp(td + WT @ td_w2))
    splitk_gemm<<<dim3(1, 32, KS_), blk>>>(WX, C_, td_w1, P2, NTOK, 64, C_);
    reduce_tanh<<<(NTOK * 64 + 255) / 256, blk>>>(P2, WT, NTOK * 64);
    gemm_decay<<<dim3(8, 32), blk>>>(WT, 64, td_w2, Wd, NTOK, C_, 64, time_decay);

    // 6. WKV scan (v-split) then groupnorm+gate
    scan_kernel2<<<128, 128>>>(Rb, Kb, Vb, Wd, time_first, Yb);
    norm_gate<<<NTOK * H_ / 8, blk>>>(Yb, Gb, ln_w, ln_b);

    // 7. output projection
    tc_gemm<0><<<dim3(8, 32), blk, tc_smem>>>(Yb, Wrn + 4 * C_ * C_, out, NTOK, C_, C_);
}

// round 7
// speedup vs baseline: 2.0818x; 1.3905x over previous
#include <cuda_runtime.h>
#include <mma.h>
#include <math.h>
#include <stdint.h>

using namespace nvcuda;

#define B_ 4
#define T_ 1024
#define C_ 1024
#define H_ 16
#define NTOK (B_*T_)
#define KS_ 4     // split-K factor for skinny GEMMs
#define NCH 8     // scan chunks
#define TCH 128   // steps per chunk

// ---------------- scratch (device globals; no allocation allowed) ----------------
__device__ float d_SX[NTOK*C_];
__device__ float d_XS[NTOK*C_];
__device__ float d_M1[NTOK*160];
__device__ float d_WX[NTOK*C_];
__device__ float d_KX[NTOK*C_];
__device__ float d_VX[NTOK*C_];
__device__ float d_RX[NTOK*C_];
__device__ float d_GX[NTOK*C_];
__device__ float d_R [NTOK*C_];
__device__ float d_K [NTOK*C_];
__device__ float d_V [NTOK*C_];
__device__ float d_G [NTOK*C_];
__device__ float d_Wd[NTOK*C_];
__device__ float d_WT[NTOK*64];
__device__ float d_Y [NTOK*C_];
__device__ float d_Wrnd[5*C_*C_];          // 5 tf32-rounded weights [K,N]
__device__ float d_P1[KS_*NTOK*160];       // split-K partials (tm)
__device__ float d_P2[KS_*NTOK*64];        // split-K partials (td)
__device__ float d_State[64*NCH*64*64];    // per-(bh,chunk) end state [k][v]
__device__ float d_SIn  [64*NCH*64*64];    // per-(bh,chunk) entry state
__device__ float d_Dp   [64*NCH*64];       // per-(bh,chunk) decay product [k]

// ---------------- helpers ----------------
__device__ __forceinline__ void cp_async16(uint32_t dst, const void* src) {
    asm volatile("cp.async.cg.shared.global [%0], [%1], 16;\n" :: "r"(dst), "l"(src));
}
__device__ __forceinline__ void cp_commit() { asm volatile("cp.async.commit_group;\n"); }
template<int N> __device__ __forceinline__ void cp_wait() {
    asm volatile("cp.async.wait_group %0;\n" :: "n"(N));
}
__device__ __forceinline__ float to_tf32(float x) {
    uint32_t r;
    asm("cvt.rna.tf32.f32 %0, %1;" : "=r"(r) : "f"(x));
    return __uint_as_float(r);
}

// ---------------- prep ----------------
__global__ void prep_kernel(const float* __restrict__ x, const float* __restrict__ xmaa,
                            float* __restrict__ SX, float* __restrict__ XS)
{
    int i4 = blockIdx.x * blockDim.x + threadIdx.x;
    int i  = i4 * 4;
    if (i >= NTOK * C_) return;
    int m = i >> 10;
    int c = i & 1023;
    int t = m & (T_ - 1);
    float4 xv = *(const float4*)(x + i);
    float4 xp = make_float4(0.f, 0.f, 0.f, 0.f);
    if (t != 0) xp = *(const float4*)(x + i - C_);
    float4 ma = *(const float4*)(xmaa + c);
    float4 sx, xs;
    sx.x = xp.x - xv.x; sx.y = xp.y - xv.y; sx.z = xp.z - xv.z; sx.w = xp.w - xv.w;
    xs.x = fmaf(sx.x, ma.x, xv.x); xs.y = fmaf(sx.y, ma.y, xv.y);
    xs.z = fmaf(sx.z, ma.z, xv.z); xs.w = fmaf(sx.w, ma.w, xv.w);
    *(float4*)(SX + i) = sx;
    *(float4*)(XS + i) = xs;
}

// ---------------- round 5 weights to tf32 ----------------
__global__ void round5(const float* __restrict__ W0, const float* __restrict__ W1,
                       const float* __restrict__ W2, const float* __restrict__ W3,
                       const float* __restrict__ W4, float* __restrict__ out)
{
    const float* srcs[5] = {W0, W1, W2, W3, W4};
    int i = (blockIdx.x * blockDim.x + threadIdx.x) * 4;
    int which = blockIdx.y;
    const float* src = srcs[which];
    float* dst = out + (size_t)which * C_ * C_;
    float4 v = *(const float4*)(src + i);
    v.x = to_tf32(v.x); v.y = to_tf32(v.y); v.z = to_tf32(v.z); v.w = to_tf32(v.w);
    *(float4*)(dst + i) = v;
}

// ---------------- split-K fp32 GEMM for skinny N ----------------
__global__ __launch_bounds__(256) void splitk_gemm(
    const float* __restrict__ A, int lda,
    const float* __restrict__ B,
    float* __restrict__ P,
    int M, int N, int K)
{
    const int BM = 128, BN = 64, BK = 16;
    __shared__ float As[BK][BM + 4];
    __shared__ float Bs[BK][BN + 4];
    int tid = threadIdx.x;
    int n0 = blockIdx.x * BN;
    int m0 = blockIdx.y * BM;
    int KC = K / gridDim.z;
    int kbeg = blockIdx.z * KC;

    int arow = tid >> 2;
    int acol = (tid & 3) << 2;
    int brow = tid >> 4;
    int bcol = (tid & 15) << 2;
    int tx = tid & 15, ty = tid >> 4;

    float acc[8][4];
    #pragma unroll
    for (int i = 0; i < 8; i++)
        #pragma unroll
        for (int j = 0; j < 4; j++) acc[i][j] = 0.f;

    for (int k0 = kbeg; k0 < kbeg + KC; k0 += BK) {
        #pragma unroll
        for (int i = 0; i < 2; i++) {
            int r = arow + i * 64;
            const float4 av = *(const float4*)(A + (size_t)(m0 + r) * lda + (k0 + acol));
            As[acol + 0][r] = av.x; As[acol + 1][r] = av.y;
            As[acol + 2][r] = av.z; As[acol + 3][r] = av.w;
        }
        {
            float4 bv = make_float4(0.f, 0.f, 0.f, 0.f);
            if (n0 + bcol < N)
                bv = *(const float4*)(B + (size_t)(k0 + brow) * N + (n0 + bcol));
            *(float4*)&Bs[brow][bcol] = bv;
        }
        __syncthreads();
        #pragma unroll
        for (int kk = 0; kk < BK; kk++) {
            float a[8], b[4];
            *(float4*)&a[0] = *(const float4*)&As[kk][ty * 8];
            *(float4*)&a[4] = *(const float4*)&As[kk][ty * 8 + 4];
            *(float4*)&b[0] = *(const float4*)&Bs[kk][tx * 4];
            #pragma unroll
            for (int i = 0; i < 8; i++)
                #pragma unroll
                for (int j = 0; j < 4; j++)
                    acc[i][j] = fmaf(a[i], b[j], acc[i][j]);
        }
        __syncthreads();
    }

    float* Pz = P + (size_t)blockIdx.z * M * N;
    #pragma unroll
    for (int i = 0; i < 8; i++) {
        int m = m0 + ty * 8 + i;
        int n = n0 + tx * 4;
        if (n < N)
            *(float4*)(Pz + (size_t)m * N + n) = *(float4*)&acc[i][0];
    }
}

// ---------------- reduce split-K partials + tanh ----------------
__global__ void reduce_tanh(const float* __restrict__ P, float* __restrict__ out, int MN)
{
    int i = blockIdx.x * blockDim.x + threadIdx.x;
    if (i >= MN) return;
    float s = 0.f;
    #pragma unroll
    for (int z = 0; z < KS_; z++) s += P[(size_t)z * MN + i];
    out[i] = tanhf(s);
}

// ---------------- fp32 GEMM with decay epilogue (K=64) ----------------
__global__ __launch_bounds__(256) void gemm_decay(
    const float* __restrict__ A, int lda,
    const float* __restrict__ B,
    float* __restrict__ C,
    int M, int N, int K,
    const float* __restrict__ e2)
{
    const int BM = 128, BN = 128, BK = 16;
    __shared__ float As[BK][BM + 4];
    __shared__ float Bs[BK][BN + 4];
    int tid = threadIdx.x;
    int m0 = blockIdx.y * BM;
    int n0 = blockIdx.x * BN;
    int tx = tid & 15, ty = tid >> 4;

    int arow = tid >> 2;
    int acol = (tid & 3) << 2;
    int brow = tid >> 5;
    int bcol = (tid & 31) << 2;

    float acc[8][8];
    #pragma unroll
    for (int i = 0; i < 8; i++)
        #pragma unroll
        for (int j = 0; j < 8; j++) acc[i][j] = 0.f;

    for (int k0 = 0; k0 < K; k0 += BK) {
        #pragma unroll
        for (int i = 0; i < 2; i++) {
            int r = arow + i * 64;
            const float4 av = *(const float4*)(A + (size_t)(m0 + r) * lda + (k0 + acol));
            As[acol + 0][r] = av.x; As[acol + 1][r] = av.y;
            As[acol + 2][r] = av.z; As[acol + 3][r] = av.w;
        }
        #pragma unroll
        for (int i = 0; i < 2; i++) {
            int r = brow + i * 8;
            float4 bv = *(const float4*)(B + (size_t)(k0 + r) * N + (n0 + bcol));
            *(float4*)&Bs[r][bcol] = bv;
        }
        __syncthreads();
        #pragma unroll
        for (int kk = 0; kk < BK; kk++) {
            float a[8], b[8];
            *(float4*)&a[0] = *(const float4*)&As[kk][ty * 8];
            *(float4*)&a[4] = *(const float4*)&As[kk][ty * 8 + 4];
            *(float4*)&b[0] = *(const float4*)&Bs[kk][tx * 8];
            *(float4*)&b[4] = *(const float4*)&Bs[kk][tx * 8 + 4];
            #pragma unroll
            for (int i = 0; i < 8; i++)
                #pragma unroll
                for (int j = 0; j < 8; j++)
                    acc[i][j] = fmaf(a[i], b[j], acc[i][j]);
        }
        __syncthreads();
    }

    #pragma unroll
    for (int i = 0; i < 8; i++) {
        int m = m0 + ty * 8 + i;
        #pragma unroll
        for (int j = 0; j < 8; j++) {
            int n = n0 + tx * 8 + j;
            C[(size_t)m * N + n] = expf(-expf(e2[n] + acc[i][j]));
        }
    }
}

// ---------------- pipelined tf32 wmma GEMM core ----------------
#define TC_STAGES 3
#define TC_ALD 20
#define TC_BLD 132
#define TC_SMEM_FLOATS (TC_STAGES * (128 * TC_ALD + 16 * TC_BLD))

__device__ __forceinline__ void tc_gemm_body(
    const float* __restrict__ A, const float* __restrict__ B, float* __restrict__ C,
    int N, int K, int m0, int n0, bool silu, float* smp)
{
    float* As = smp;
    float* Bs = smp + TC_STAGES * 128 * TC_ALD;

    int tid = threadIdx.x;
    int wid = tid >> 5;
    int lane = tid & 31;
    int wm = wid >> 2;
    int wn = wid & 3;

    wmma::fragment<wmma::accumulator, 16, 16, 8, float> acc[4][2];
    #pragma unroll
    for (int i = 0; i < 4; i++)
        #pragma unroll
        for (int j = 0; j < 2; j++) wmma::fill_fragment(acc[i][j], 0.f);

    const int KT = K >> 4;

    auto load_tile = [&](int t, int s) {
        int k0 = t << 4;
        #pragma unroll
        for (int i = 0; i < 2; i++) {
            int c = tid + i * 256;
            int row = c >> 2;
            int kc  = (c & 3) << 2;
            uint32_t dst = (uint32_t)__cvta_generic_to_shared(
                As + ((size_t)(s * 128 + row)) * TC_ALD + kc);
            cp_async16(dst, A + (size_t)(m0 + row) * K + (k0 + kc));
        }
        #pragma unroll
        for (int i = 0; i < 2; i++) {
            int c = tid + i * 256;
            int kr = c >> 5;
            int nc = (c & 31) << 2;
            uint32_t dst = (uint32_t)__cvta_generic_to_shared(
                Bs + ((size_t)(s * 16 + kr)) * TC_BLD + nc);
            cp_async16(dst, B + (size_t)(k0 + kr) * N + (n0 + nc));
        }
    };

    load_tile(0, 0); cp_commit();
    load_tile(1, 1); cp_commit();

    for (int t = 0; t < KT; ++t) {
        int s = t % TC_STAGES;
        cp_wait<TC_STAGES - 2>();
        __syncthreads();
        int pt = t + TC_STAGES - 1;
        if (pt < KT) load_tile(pt, pt % TC_STAGES);
        cp_commit();

        #pragma unroll
        for (int kk = 0; kk < 16; kk += 8) {
            wmma::fragment<wmma::matrix_a, 16, 16, 8, wmma::precision::tf32, wmma::row_major> af[4];
            wmma::fragment<wmma::matrix_b, 16, 16, 8, wmma::precision::tf32, wmma::row_major> bf[2];
            #pragma unroll
            for (int i = 0; i < 4; i++)
                wmma::load_matrix_sync(af[i], As + ((size_t)(s * 128 + wm * 64 + i * 16)) * TC_ALD + kk, TC_ALD);
            #pragma unroll
            for (int j = 0; j < 2; j++)
                wmma::load_matrix_sync(bf[j], Bs + ((size_t)(s * 16 + kk)) * TC_BLD + wn * 32 + j * 16, TC_BLD);
            #pragma unroll
            for (int i = 0; i < 4; i++)
                #pragma unroll
                for (int j = 0; j < 2; j++)
                    wmma::mma_sync(acc[i][j], af[i], bf[j], acc[i][j]);
        }
    }
    cp_wait<0>();
    __syncthreads();

    float* stg = smp + wid * 16 * 20;

    #pragma unroll
    for (int i = 0; i < 4; i++) {
        #pragma unroll
        for (int j = 0; j < 2; j++) {
            int mb = m0 + wm * 64 + i * 16;
            int nb = n0 + wn * 32 + j * 16;
            if (!silu) {
                wmma::store_matrix_sync(C + (size_t)mb * N + nb, acc[i][j], N, wmma::mem_row_major);
            } else {
                wmma::store_matrix_sync(stg, acc[i][j], 20, wmma::mem_row_major);
                __syncwarp();
                int r  = lane >> 1;
                int c0 = (lane & 1) * 8;
                #pragma unroll
                for (int q = 0; q < 8; q++) {
                    float v = stg[r * 20 + c0 + q];
                    C[(size_t)(mb + r) * N + (nb + c0 + q)] = v / (1.f + expf(-v));
                }
                __syncwarp();
            }
        }
    }
}

// single GEMM (Wo)
__global__ __launch_bounds__(256) void tc_gemm(
    const float* __restrict__ A, const float* __restrict__ B,
    float* __restrict__ C, int M, int N, int K)
{
    extern __shared__ float smp[];
    tc_gemm_body(A, B, C, N, K, blockIdx.y * 128, blockIdx.x * 128, false, smp);
}

// z-batched 4 projections (R,K,V,G) — G gets silu
struct Batch4 {
    const float *A0, *A1, *A2, *A3;
    float *C0, *C1, *C2, *C3;
};
__global__ __launch_bounds__(256) void tc_gemm_b4(
    Batch4 p, const float* __restrict__ Wbase, int M, int N, int K)
{
    extern __shared__ float smp[];
    int z = blockIdx.z;
    const float* A = (z == 0) ? p.A0 : (z == 1) ? p.A1 : (z == 2) ? p.A2 : p.A3;
    float*       C = (z == 0) ? p.C0 : (z == 1) ? p.C1 : (z == 2) ? p.C2 : p.C3;
    const float* B = Wbase + (size_t)z * C_ * C_;
    tc_gemm_body(A, B, C, N, K, blockIdx.y * 128, blockIdx.x * 128, z == 3, smp);
}

// ---------------- fused mix: 5 outputs in one pass ----------------
__global__ __launch_bounds__(256) void mix_fused(
    const float* __restrict__ M1,
    const float* __restrict__ W2,
    const float* __restrict__ x, const float* __restrict__ SX,
    const float* __restrict__ wmaa, const float* __restrict__ kmaa,
    const float* __restrict__ vmaa, const float* __restrict__ rmaa,
    const float* __restrict__ gmaa,
    float* __restrict__ WX, float* __restrict__ KX, float* __restrict__ VX,
    float* __restrict__ RX, float* __restrict__ GX)
{
    __shared__ float M1s[64][33];
    __shared__ float W2s[32][68];
    int tid = threadIdx.x;
    int m0 = blockIdx.y * 64, n0 = blockIdx.x * 64;
    int tx = tid & 15, ty = tid >> 4;

    float4 xr[4], sxr[4];
    #pragma unroll
    for (int i = 0; i < 4; i++) {
        size_t idx = (size_t)(m0 + ty * 4 + i) * C_ + n0 + tx * 4;
        xr[i]  = *(const float4*)(x + idx);
        sxr[i] = *(const float4*)(SX + idx);
    }

    const float* maap[5] = {wmaa, kmaa, vmaa, rmaa, gmaa};
    float* outp[5] = {WX, KX, VX, RX, GX};

    for (int f = 0; f < 5; f++) {
        #pragma unroll
        for (int i = 0; i < 2; i++) {
            int c = tid + i * 256;
            int r = c >> 3, cc = (c & 7) << 2;
            float4 v4 = *(const float4*)(M1 + (size_t)(m0 + r) * 160 + f * 32 + cc);
            M1s[r][cc] = v4.x; M1s[r][cc + 1] = v4.y; M1s[r][cc + 2] = v4.z; M1s[r][cc + 3] = v4.w;
        }
        #pragma unroll
        for (int i = 0; i < 2; i++) {
            int c = tid + i * 256;
            int r = c >> 4, cc = (c & 15) << 2;
            float4 v4 = *(const float4*)(W2 + (size_t)(f * 32 + r) * C_ + n0 + cc);
            W2s[r][cc] = v4.x; W2s[r][cc + 1] = v4.y; W2s[r][cc + 2] = v4.z; W2s[r][cc + 3] = v4.w;
        }
        __syncthreads();

        float acc[4][4];
        #pragma unroll
        for (int i = 0; i < 4; i++)
            #pragma unroll
            for (int j = 0; j < 4; j++) acc[i][j] = 0.f;

        #pragma unroll
        for (int k = 0; k < 32; k++) {
            float a[4], b[4];
            #pragma unroll
            for (int i = 0; i < 4; i++) a[i] = M1s[ty * 4 + i][k];
            #pragma unroll
            for (int j = 0; j < 4; j++) b[j] = W2s[k][tx * 4 + j];
            #pragma unroll
            for (int i = 0; i < 4; i++)
                #pragma unroll
                for (int j = 0; j < 4; j++)
                    acc[i][j] = fmaf(a[i], b[j], acc[i][j]);
        }

        float4 mv = *(const float4*)(maap[f] + n0 + tx * 4);
        float* op = outp[f];
        bool rnd = (f >= 1);
        #pragma unroll
        for (int i = 0; i < 4; i++) {
            size_t idx = (size_t)(m0 + ty * 4 + i) * C_ + n0 + tx * 4;
            float4 o;
            const float* xi = (const float*)&xr[i];
            const float* si = (const float*)&sxr[i];
            const float* mi = (const float*)&mv;
            float* oo = (float*)&o;
            #pragma unroll
            for (int j = 0; j < 4; j++) {
                float v = fmaf(si[j], mi[j] + acc[i][j], xi[j]);
                oo[j] = rnd ? to_tf32(v) : v;
            }
            *(float4*)(op + idx) = o;
        }
        __syncthreads();
    }
}

// ---------------- chunked WKV scan ----------------
// phase 1: per-(bh,chunk) scan from zero state; writes partial Y and end state
__global__ __launch_bounds__(256) void scanA(
    const float* __restrict__ R, const float* __restrict__ Kt,
    const float* __restrict__ V, const float* __restrict__ W,
    const float* __restrict__ u,
    float* __restrict__ Y, float* __restrict__ S)
{
    int blk = blockIdx.x;            // bh*NCH + ch
    int bh = blk >> 3, ch = blk & 7;
    int b = bh >> 4, h = bh & 15;
    int tid = threadIdx.x;
    int kq = tid >> 6, v = tid & 63;

    __shared__ float r_s[64], k_s[64], w_s[64], v_s[64];
    __shared__ float red[256];

    float u_r[16];
    #pragma unroll
    for (int i = 0; i < 16; i++) u_r[i] = u[h * 64 + kq * 16 + i];

    float st[16];
    #pragma unroll
    for (int i = 0; i < 16; i++) st[i] = 0.f;

    const size_t base = (size_t)b * T_ * C_ + (size_t)h * 64 + (size_t)(ch * TCH) * C_;
    const float* src = (tid < 64) ? R : (tid < 128) ? Kt : (tid < 192) ? W : V;
    int c = tid & 63;
    float pre = src[base + c];

    for (int t = 0; t < TCH; ++t) {
        if (tid < 64)       r_s[c] = pre;
        else if (tid < 128) k_s[c] = pre;
        else if (tid < 192) w_s[c] = pre;
        else                v_s[c] = pre;
        __syncthreads();

        if (t < TCH - 1) pre = src[base + (size_t)(t + 1) * C_ + c];

        float vv = v_s[v];
        float y = 0.f;
        #pragma unroll
        for (int i = 0; i < 16; i++) {
            int kk = kq * 16 + i;
            float a = k_s[kk] * vv;
            y = fmaf(r_s[kk], fmaf(u_r[i], a, st[i]), y);
            st[i] = fmaf(w_s[kk], st[i], a);
        }
        red[tid] = y;
        __syncthreads();

        if (kq == 0) {
            float ys = ((red[v] + red[64 + v]) + (red[128 + v] + red[192 + v])) * 0.125f;
            Y[base + (size_t)t * C_ + v] = ys;
        }
    }

    float* Sp = S + (((size_t)blk * 64) + kq * 16) * 64 + v;
    #pragma unroll
    for (int i = 0; i < 16; i++) Sp[(size_t)i * 64] = st[i];
}

// per-chunk decay products D[blk][k] = prod_t w
__global__ void decay_prod(const float* __restrict__ Wd, float* __restrict__ Dp)
{
    int blk = blockIdx.x;
    int bh = blk >> 3, ch = blk & 7;
    int b = bh >> 4, h = bh & 15;
    int k = threadIdx.x;   // 64
    size_t base = (size_t)b * T_ * C_ + (size_t)h * 64 + (size_t)(ch * TCH) * C_ + k;
    float p0 = 1.f, p1 = 1.f, p2 = 1.f, p3 = 1.f;
    for (int t = 0; t < TCH; t += 4) {
        p0 *= Wd[base + (size_t)t * C_];
        p1 *= Wd[base + (size_t)(t + 1) * C_];
        p2 *= Wd[base + (size_t)(t + 2) * C_];
        p3 *= Wd[base + (size_t)(t + 3) * C_];
    }
    Dp[blk * 64 + k] = (p0 * p1) * (p2 * p3);
}

// phase 2: chunk-level recurrence in_{c+1} = D_c ⊙ in_c + S_c
__global__ __launch_bounds__(256) void scanB(
    const float* __restrict__ S, const float* __restrict__ Dp, float* __restrict__ SIn)
{
    int bh = blockIdx.x;
    int tid = threadIdx.x;
    int kq = tid >> 6, v = tid & 63;
    float in[16];
    #pragma unroll
    for (int i = 0; i < 16; i++) in[i] = 0.f;

    for (int cc = 0; cc < NCH - 1; cc++) {
        const float* Sp = S + (((size_t)(bh * NCH + cc) * 64) + kq * 16) * 64 + v;
        const float* Dq = Dp + (bh * NCH + cc) * 64 + kq * 16;
        float* Op = SIn + (((size_t)(bh * NCH + cc + 1) * 64) + kq * 16) * 64 + v;
        #pragma unroll
        for (int i = 0; i < 16; i++)
            in[i] = fmaf(Dq[i], in[i], Sp[(size_t)i * 64]);
        #pragma unroll
        for (int i = 0; i < 16; i++)
            Op[(size_t)i * 64] = in[i];
    }
}

// phase 3: homogeneous correction — y += r · (in ⊙ running decay)
__global__ __launch_bounds__(256) void scanC(
    const float* __restrict__ R, const float* __restrict__ W,
    const float* __restrict__ SIn, float* __restrict__ Y)
{
    int blk = blockIdx.x;            // bh*(NCH-1) + (ch-1)
    int bh = blk / (NCH - 1);
    int ch = blk % (NCH - 1) + 1;
    int b = bh >> 4, h = bh & 15;
    int tid = threadIdx.x;
    int kq = tid >> 6, v = tid & 63;

    __shared__ float r_s[64], w_s[64];
    __shared__ float red[256];

    float s2[16];
    const float* Ip = SIn + (((size_t)(bh * NCH + ch) * 64) + kq * 16) * 64 + v;
    #pragma unroll
    for (int i = 0; i < 16; i++) s2[i] = Ip[(size_t)i * 64];

    const size_t base = (size_t)b * T_ * C_ + (size_t)h * 64 + (size_t)(ch * TCH) * C_;
    float pre = 0.f;
    if (tid < 128) {
        const float* src = (tid < 64) ? R : W;
        pre = src[base + (tid & 63)];
    }

    for (int t = 0; t < TCH; ++t) {
        if (tid < 64)       r_s[tid] = pre;
        else if (tid < 128) w_s[tid - 64] = pre;
        __syncthreads();

        if (t < TCH - 1 && tid < 128) {
            const float* src = (tid < 64) ? R : W;
            pre = src[base + (size_t)(t + 1) * C_ + (tid & 63)];
        }

        float y = 0.f;
        #pragma unroll
        for (int i = 0; i < 16; i++) {
            int kk = kq * 16 + i;
            y = fmaf(r_s[kk], s2[i], y);
            s2[i] *= w_s[kk];
        }
        red[tid] = y;
        __syncthreads();

        if (kq == 0) {
            float ys = ((red[v] + red[64 + v]) + (red[128 + v] + red[192 + v])) * 0.125f;
            size_t yi = base + (size_t)t * C_ + v;
            Y[yi] += ys;
        }
    }
}

// ---------------- groupnorm + ln affine + gate (in-place on Y, tf32-rounded) ----------------
__global__ __launch_bounds__(256) void norm_gate(
    float* __restrict__ Y, const float* __restrict__ G,
    const float* __restrict__ lnw, const float* __restrict__ lnb)
{
    int wid = threadIdx.x >> 5;
    int lane = threadIdx.x & 31;
    int gi = blockIdx.x * 8 + wid;
    int m = gi >> 4, h = gi & 15;
    size_t p = (size_t)m * C_ + h * 64;

    float a = Y[p + lane], b2 = Y[p + 32 + lane];
    float s1 = a + b2;
    float s2 = a * a + b2 * b2;
    #pragma unroll
    for (int o = 16; o > 0; o >>= 1) {
        s1 += __shfl_xor_sync(0xffffffffu, s1, o);
        s2 += __shfl_xor_sync(0xffffffffu, s2, o);
    }
    float mean = s1 * (1.f / 64.f);
    float var  = s2 * (1.f / 64.f) - mean * mean;
    float rs = rsqrtf(var + 1e-5f);

    int c0 = h * 64 + lane;
    float o1 = fmaf((a  - mean) * rs, lnw[c0],      lnb[c0])      * G[p + lane];
    float o2 = fmaf((b2 - mean) * rs, lnw[c0 + 32], lnb[c0 + 32]) * G[p + 32 + lane];
    Y[p + lane]      = to_tf32(o1);
    Y[p + 32 + lane] = to_tf32(o2);
}

// ---------------- launch ----------------
extern "C" void kernel_launch(void* const* d_in, const int* in_sizes, int n_in,
                              void* d_out, int out_size)
{
    (void)in_sizes; (void)n_in; (void)out_size;
    const float* x          = (const float*)d_in[0];
    const float* x_maa      = (const float*)d_in[1];
    const float* w_maa      = (const float*)d_in[2];
    const float* k_maa      = (const float*)d_in[3];
    const float* v_maa      = (const float*)d_in[4];
    const float* r_maa      = (const float*)d_in[5];
    const float* g_maa      = (const float*)d_in[6];
    const float* tm_w1      = (const float*)d_in[7];
    const float* tm_w2      = (const float*)d_in[8];
    const float* td_w1      = (const float*)d_in[9];
    const float* td_w2      = (const float*)d_in[10];
    const float* time_decay = (const float*)d_in[11];
    const float* time_first = (const float*)d_in[12];
    const float* Wr         = (const float*)d_in[13];
    const float* Wk         = (const float*)d_in[14];
    const float* Wv         = (const float*)d_in[15];
    const float* Wg         = (const float*)d_in[16];
    const float* Wo         = (const float*)d_in[17];
    const float* ln_w       = (const float*)d_in[18];
    const float* ln_b       = (const float*)d_in[19];
    float* out = (float*)d_out;

    float *SX, *XS, *M1, *WX, *KX, *VX, *RX, *GX, *Rb, *Kb, *Vb, *Gb, *Wd, *WT, *Yb,
          *Wrn, *P1, *P2, *St, *SIn, *Dp;
    cudaGetSymbolAddress((void**)&SX, d_SX);
    cudaGetSymbolAddress((void**)&XS, d_XS);
    cudaGetSymbolAddress((void**)&M1, d_M1);
    cudaGetSymbolAddress((void**)&WX, d_WX);
    cudaGetSymbolAddress((void**)&KX, d_KX);
    cudaGetSymbolAddress((void**)&VX, d_VX);
    cudaGetSymbolAddress((void**)&RX, d_RX);
    cudaGetSymbolAddress((void**)&GX, d_GX);
    cudaGetSymbolAddress((void**)&Rb, d_R);
    cudaGetSymbolAddress((void**)&Kb, d_K);
    cudaGetSymbolAddress((void**)&Vb, d_V);
    cudaGetSymbolAddress((void**)&Gb, d_G);
    cudaGetSymbolAddress((void**)&Wd, d_Wd);
    cudaGetSymbolAddress((void**)&WT, d_WT);
    cudaGetSymbolAddress((void**)&Yb, d_Y);
    cudaGetSymbolAddress((void**)&Wrn, d_Wrnd);
    cudaGetSymbolAddress((void**)&P1, d_P1);
    cudaGetSymbolAddress((void**)&P2, d_P2);
    cudaGetSymbolAddress((void**)&St, d_State);
    cudaGetSymbolAddress((void**)&SIn, d_SIn);
    cudaGetSymbolAddress((void**)&Dp, d_Dp);

    const int tc_smem = TC_SMEM_FLOATS * (int)sizeof(float);
    cudaFuncSetAttribute(tc_gemm,    cudaFuncAttributeMaxDynamicSharedMemorySize, tc_smem);
    cudaFuncSetAttribute(tc_gemm_b4, cudaFuncAttributeMaxDynamicSharedMemorySize, tc_smem);

    dim3 blk(256);

    // 0. tf32-round weights: order r,k,v,g,o
    round5<<<dim3(C_ * C_ / 4 / 256, 5), blk>>>(Wr, Wk, Wv, Wg, Wo, Wrn);

    // 1. prep
    prep_kernel<<<(NTOK * C_ / 4 + 255) / 256, blk>>>(x, x_maa, SX, XS);

    // 2. M1 = tanh(XS @ tm_w1)   [4096,160]  (split-K)
    splitk_gemm<<<dim3(3, 32, KS_), blk>>>(XS, C_, tm_w1, P1, NTOK, 160, C_);
    reduce_tanh<<<(NTOK * 160 + 255) / 256, blk>>>(P1, M1, NTOK * 160);

    // 3. fused mix -> WX,KX,VX,RX,GX
    mix_fused<<<dim3(16, 64), blk>>>(M1, tm_w2, x, SX,
                                     w_maa, k_maa, v_maa, r_maa, g_maa,
                                     WX, KX, VX, RX, GX);

    // 4. projections: batched R,K,V,G (G=silu)
    Batch4 bp { RX, KX, VX, GX, Rb, Kb, Vb, Gb };
    tc_gemm_b4<<<dim3(8, 32, 4), blk, tc_smem>>>(bp, Wrn, NTOK, C_, C_);

    // 5. decay LoRA: WT = tanh(WX @ td_w1) (split-K); Wd = exp(-exp(td + WT @ td_w2))
    splitk_gemm<<<dim3(1, 32, KS_), blk>>>(WX, C_, td_w1, P2, NTOK, 64, C_);
    reduce_tanh<<<(NTOK * 64 + 255) / 256, blk>>>(P2, WT, NTOK * 64);
    gemm_decay<<<dim3(8, 32), blk>>>(WT, 64, td_w2, Wd, NTOK, C_, 64, time_decay);

    // 6. chunked WKV scan, then groupnorm+gate
    scanA<<<64 * NCH, blk>>>(Rb, Kb, Vb, Wd, time_first, Yb, St);
    decay_prod<<<64 * NCH, 64>>>(Wd, Dp);
    scanB<<<64, blk>>>(St, Dp, SIn);
    scanC<<<64 * (NCH - 1), blk>>>(Rb, Wd, SIn, Yb);
    norm_gate<<<NTOK * H_ / 8, blk>>>(Yb, Gb, ln_w, ln_b);

    // 7. output projection
    tc_gemm<<<dim3(8, 32), blk, tc_smem>>>(Yb, Wrn + 4 * (size_t)C_ * C_, out, NTOK, C_, C_);
}

// round 8
// speedup vs baseline: 2.1087x; 1.0129x over previous
#include <cuda_runtime.h>
#include <mma.h>
#include <math.h>
#include <stdint.h>

using namespace nvcuda;

#define B_ 4
#define T_ 1024
#define C_ 1024
#define H_ 16
#define NTOK (B_*T_)
#define KS_ 4     // split-K factor for skinny GEMMs
#define NCH 8     // scan chunks
#define TCH 128   // steps per chunk

// ---------------- scratch (device globals; no allocation allowed) ----------------
__device__ float d_SX[NTOK*C_];
__device__ float d_XS[NTOK*C_];
__device__ float d_M1[NTOK*160];
__device__ float d_WX[NTOK*C_];
__device__ float d_KX[NTOK*C_];
__device__ float d_VX[NTOK*C_];
__device__ float d_RX[NTOK*C_];
__device__ float d_GX[NTOK*C_];
__device__ float d_R [NTOK*C_];
__device__ float d_K [NTOK*C_];
__device__ float d_V [NTOK*C_];
__device__ float d_G [NTOK*C_];
__device__ float d_Wd[NTOK*C_];
__device__ float d_WT[NTOK*64];
__device__ float d_Y [NTOK*C_];
__device__ float d_Wrnd[5*C_*C_];          // 5 tf32-rounded weights [K,N]
__device__ float d_P1[KS_*NTOK*160];       // split-K partials (tm)
__device__ float d_P2[KS_*NTOK*64];        // split-K partials (td)
__device__ float d_State[64*NCH*64*64];    // per-(bh,chunk) end state [k][v]
__device__ float d_SIn  [64*NCH*64*64];    // per-(bh,chunk) entry state
__device__ float d_Dp   [64*NCH*64];       // per-(bh,chunk) decay product [k]

// ---------------- helpers ----------------
__device__ __forceinline__ void cp_async16(uint32_t dst, const void* src) {
    asm volatile("cp.async.cg.shared.global [%0], [%1], 16;\n" :: "r"(dst), "l"(src));
}
__device__ __forceinline__ void cp_commit() { asm volatile("cp.async.commit_group;\n"); }
template<int N> __device__ __forceinline__ void cp_wait() {
    asm volatile("cp.async.wait_group %0;\n" :: "n"(N));
}
__device__ __forceinline__ float to_tf32(float x) {
    uint32_t r;
    asm("cvt.rna.tf32.f32 %0, %1;" : "=r"(r) : "f"(x));
    return __uint_as_float(r);
}

// ---------------- prep ----------------
__global__ void prep_kernel(const float* __restrict__ x, const float* __restrict__ xmaa,
                            float* __restrict__ SX, float* __restrict__ XS)
{
    int i4 = blockIdx.x * blockDim.x + threadIdx.x;
    int i  = i4 * 4;
    if (i >= NTOK * C_) return;
    int m = i >> 10;
    int c = i & 1023;
    int t = m & (T_ - 1);
    float4 xv = *(const float4*)(x + i);
    float4 xp = make_float4(0.f, 0.f, 0.f, 0.f);
    if (t != 0) xp = *(const float4*)(x + i - C_);
    float4 ma = *(const float4*)(xmaa + c);
    float4 sx, xs;
    sx.x = xp.x - xv.x; sx.y = xp.y - xv.y; sx.z = xp.z - xv.z; sx.w = xp.w - xv.w;
    xs.x = fmaf(sx.x, ma.x, xv.x); xs.y = fmaf(sx.y, ma.y, xv.y);
    xs.z = fmaf(sx.z, ma.z, xv.z); xs.w = fmaf(sx.w, ma.w, xv.w);
    *(float4*)(SX + i) = sx;
    *(float4*)(XS + i) = xs;
}

// ---------------- round 5 weights to tf32 ----------------
__global__ void round5(const float* __restrict__ W0, const float* __restrict__ W1,
                       const float* __restrict__ W2, const float* __restrict__ W3,
                       const float* __restrict__ W4, float* __restrict__ out)
{
    const float* srcs[5] = {W0, W1, W2, W3, W4};
    int i = (blockIdx.x * blockDim.x + threadIdx.x) * 4;
    int which = blockIdx.y;
    const float* src = srcs[which];
    float* dst = out + (size_t)which * C_ * C_;
    float4 v = *(const float4*)(src + i);
    v.x = to_tf32(v.x); v.y = to_tf32(v.y); v.z = to_tf32(v.z); v.w = to_tf32(v.w);
    *(float4*)(dst + i) = v;
}

// ---------------- split-K fp32 GEMM for skinny N ----------------
__global__ __launch_bounds__(256) void splitk_gemm(
    const float* __restrict__ A, int lda,
    const float* __restrict__ B,
    float* __restrict__ P,
    int M, int N, int K)
{
    const int BM = 128, BN = 64, BK = 16;
    __shared__ float As[BK][BM + 4];
    __shared__ float Bs[BK][BN + 4];
    int tid = threadIdx.x;
    int n0 = blockIdx.x * BN;
    int m0 = blockIdx.y * BM;
    int KC = K / gridDim.z;
    int kbeg = blockIdx.z * KC;

    int arow = tid >> 2;
    int acol = (tid & 3) << 2;
    int brow = tid >> 4;
    int bcol = (tid & 15) << 2;
    int tx = tid & 15, ty = tid >> 4;

    float acc[8][4];
    #pragma unroll
    for (int i = 0; i < 8; i++)
        #pragma unroll
        for (int j = 0; j < 4; j++) acc[i][j] = 0.f;

    for (int k0 = kbeg; k0 < kbeg + KC; k0 += BK) {
        #pragma unroll
        for (int i = 0; i < 2; i++) {
            int r = arow + i * 64;
            const float4 av = *(const float4*)(A + (size_t)(m0 + r) * lda + (k0 + acol));
            As[acol + 0][r] = av.x; As[acol + 1][r] = av.y;
            As[acol + 2][r] = av.z; As[acol + 3][r] = av.w;
        }
        {
            float4 bv = make_float4(0.f, 0.f, 0.f, 0.f);
            if (n0 + bcol < N)
                bv = *(const float4*)(B + (size_t)(k0 + brow) * N + (n0 + bcol));
            *(float4*)&Bs[brow][bcol] = bv;
        }
        __syncthreads();
        #pragma unroll
        for (int kk = 0; kk < BK; kk++) {
            float a[8], b[4];
            *(float4*)&a[0] = *(const float4*)&As[kk][ty * 8];
            *(float4*)&a[4] = *(const float4*)&As[kk][ty * 8 + 4];
            *(float4*)&b[0] = *(const float4*)&Bs[kk][tx * 4];
            #pragma unroll
            for (int i = 0; i < 8; i++)
                #pragma unroll
                for (int j = 0; j < 4; j++)
                    acc[i][j] = fmaf(a[i], b[j], acc[i][j]);
        }
        __syncthreads();
    }

    float* Pz = P + (size_t)blockIdx.z * M * N;
    #pragma unroll
    for (int i = 0; i < 8; i++) {
        int m = m0 + ty * 8 + i;
        int n = n0 + tx * 4;
        if (n < N)
            *(float4*)(Pz + (size_t)m * N + n) = *(float4*)&acc[i][0];
    }
}

// ---------------- reduce split-K partials + tanh ----------------
__global__ void reduce_tanh(const float* __restrict__ P, float* __restrict__ out, int MN)
{
    int i = blockIdx.x * blockDim.x + threadIdx.x;
    if (i >= MN) return;
    float s = 0.f;
    #pragma unroll
    for (int z = 0; z < KS_; z++) s += P[(size_t)z * MN + i];
    out[i] = tanhf(s);
}

// ---------------- fp32 GEMM with decay epilogue (K=64) ----------------
__global__ __launch_bounds__(256) void gemm_decay(
    const float* __restrict__ A, int lda,
    const float* __restrict__ B,
    float* __restrict__ C,
    int M, int N, int K,
    const float* __restrict__ e2)
{
    const int BM = 128, BN = 128, BK = 16;
    __shared__ float As[BK][BM + 4];
    __shared__ float Bs[BK][BN + 4];
    int tid = threadIdx.x;
    int m0 = blockIdx.y * BM;
    int n0 = blockIdx.x * BN;
    int tx = tid & 15, ty = tid >> 4;

    int arow = tid >> 2;
    int acol = (tid & 3) << 2;
    int brow = tid >> 5;
    int bcol = (tid & 31) << 2;

    float acc[8][8];
    #pragma unroll
    for (int i = 0; i < 8; i++)
        #pragma unroll
        for (int j = 0; j < 8; j++) acc[i][j] = 0.f;

    for (int k0 = 0; k0 < K; k0 += BK) {
        #pragma unroll
        for (int i = 0; i < 2; i++) {
            int r = arow + i * 64;
            const float4 av = *(const float4*)(A + (size_t)(m0 + r) * lda + (k0 + acol));
            As[acol + 0][r] = av.x; As[acol + 1][r] = av.y;
            As[acol + 2][r] = av.z; As[acol + 3][r] = av.w;
        }
        #pragma unroll
        for (int i = 0; i < 2; i++) {
            int r = brow + i * 8;
            float4 bv = *(const float4*)(B + (size_t)(k0 + r) * N + (n0 + bcol));
            *(float4*)&Bs[r][bcol] = bv;
        }
        __syncthreads();
        #pragma unroll
        for (int kk = 0; kk < BK; kk++) {
            float a[8], b[8];
            *(float4*)&a[0] = *(const float4*)&As[kk][ty * 8];
            *(float4*)&a[4] = *(const float4*)&As[kk][ty * 8 + 4];
            *(float4*)&b[0] = *(const float4*)&Bs[kk][tx * 8];
            *(float4*)&b[4] = *(const float4*)&Bs[kk][tx * 8 + 4];
            #pragma unroll
            for (int i = 0; i < 8; i++)
                #pragma unroll
                for (int j = 0; j < 8; j++)
                    acc[i][j] = fmaf(a[i], b[j], acc[i][j]);
        }
        __syncthreads();
    }

    #pragma unroll
    for (int i = 0; i < 8; i++) {
        int m = m0 + ty * 8 + i;
        #pragma unroll
        for (int j = 0; j < 8; j++) {
            int n = n0 + tx * 8 + j;
            C[(size_t)m * N + n] = expf(-expf(e2[n] + acc[i][j]));
        }
    }
}

// ---------------- pipelined tf32 wmma GEMM core (BK=32, 3 stages, 2 CTAs/SM) ----------------
#define TC_STAGES 3
#define TC_ALD 36      // 32 k-floats + 4 pad
#define TC_BLD 132     // 128 n-floats + 4 pad
#define TC_SMEM_FLOATS (TC_STAGES * (128 * TC_ALD + 32 * TC_BLD))

__device__ __forceinline__ void tc_gemm_body(
    const float* __restrict__ A, const float* __restrict__ B, float* __restrict__ C,
    int N, int K, int m0, int n0, bool silu, float* smp)
{
    float* As = smp;                              // [S][128][36]
    float* Bs = smp + TC_STAGES * 128 * TC_ALD;   // [S][32][132]

    int tid = threadIdx.x;
    int wid = tid >> 5;
    int lane = tid & 31;
    int wm = wid >> 2;   // 0..1  (64-row slab)
    int wn = wid & 3;    // 0..3  (32-col slab)

    wmma::fragment<wmma::accumulator, 16, 16, 8, float> acc[4][2];
    #pragma unroll
    for (int i = 0; i < 4; i++)
        #pragma unroll
        for (int j = 0; j < 2; j++) wmma::fill_fragment(acc[i][j], 0.f);

    const int KT = K >> 5;   // BK=32

    auto load_tile = [&](int t, int s) {
        int k0 = t << 5;
        #pragma unroll
        for (int i = 0; i < 4; i++) {           // A: 128 rows x 32 floats
            int c = tid + i * 256;
            int row = c >> 3;
            int kc  = (c & 7) << 2;
            uint32_t dst = (uint32_t)__cvta_generic_to_shared(
                As + ((size_t)(s * 128 + row)) * TC_ALD + kc);
            cp_async16(dst, A + (size_t)(m0 + row) * K + (k0 + kc));
        }
        #pragma unroll
        for (int i = 0; i < 4; i++) {           // B: 32 rows x 128 floats
            int c = tid + i * 256;
            int kr = c >> 5;
            int nc = (c & 31) << 2;
            uint32_t dst = (uint32_t)__cvta_generic_to_shared(
                Bs + ((size_t)(s * 32 + kr)) * TC_BLD + nc);
            cp_async16(dst, B + (size_t)(k0 + kr) * N + (n0 + nc));
        }
    };

    load_tile(0, 0); cp_commit();
    load_tile(1, 1); cp_commit();

    for (int t = 0; t < KT; ++t) {
        int s = t % TC_STAGES;
        cp_wait<1>();
        __syncthreads();
        int pt = t + 2;
        if (pt < KT) load_tile(pt, pt % TC_STAGES);
        cp_commit();

        #pragma unroll
        for (int kk = 0; kk < 32; kk += 8) {
            wmma::fragment<wmma::matrix_a, 16, 16, 8, wmma::precision::tf32, wmma::row_major> af[4];
            wmma::fragment<wmma::matrix_b, 16, 16, 8, wmma::precision::tf32, wmma::row_major> bf[2];
            #pragma unroll
            for (int i = 0; i < 4; i++)
                wmma::load_matrix_sync(af[i], As + ((size_t)(s * 128 + wm * 64 + i * 16)) * TC_ALD + kk, TC_ALD);
            #pragma unroll
            for (int j = 0; j < 2; j++)
                wmma::load_matrix_sync(bf[j], Bs + ((size_t)(s * 32 + kk)) * TC_BLD + wn * 32 + j * 16, TC_BLD);
            #pragma unroll
            for (int i = 0; i < 4; i++)
                #pragma unroll
                for (int j = 0; j < 2; j++)
                    wmma::mma_sync(acc[i][j], af[i], bf[j], acc[i][j]);
        }
    }
    cp_wait<0>();
    __syncthreads();

    float* stg = smp + wid * 16 * 20;

    #pragma unroll
    for (int i = 0; i < 4; i++) {
        #pragma unroll
        for (int j = 0; j < 2; j++) {
            int mb = m0 + wm * 64 + i * 16;
            int nb = n0 + wn * 32 + j * 16;
            if (!silu) {
                wmma::store_matrix_sync(C + (size_t)mb * N + nb, acc[i][j], N, wmma::mem_row_major);
            } else {
                wmma::store_matrix_sync(stg, acc[i][j], 20, wmma::mem_row_major);
                __syncwarp();
                int r  = lane >> 1;
                int c0 = (lane & 1) * 8;
                #pragma unroll
                for (int q = 0; q < 8; q++) {
                    float v = stg[r * 20 + c0 + q];
                    C[(size_t)(mb + r) * N + (nb + c0 + q)] = v / (1.f + expf(-v));
                }
                __syncwarp();
            }
        }
    }
}

// single GEMM (Wo)
__global__ __launch_bounds__(256, 2) void tc_gemm(
    const float* __restrict__ A, const float* __restrict__ B,
    float* __restrict__ C, int M, int N, int K)
{
    extern __shared__ float smp[];
    tc_gemm_body(A, B, C, N, K, blockIdx.y * 128, blockIdx.x * 128, false, smp);
}

// z-batched 4 projections (R,K,V,G) — G gets silu
struct Batch4 {
    const float *A0, *A1, *A2, *A3;
    float *C0, *C1, *C2, *C3;
};
__global__ __launch_bounds__(256, 2) void tc_gemm_b4(
    Batch4 p, const float* __restrict__ Wbase, int M, int N, int K)
{
    extern __shared__ float smp[];
    int z = blockIdx.z;
    const float* A = (z == 0) ? p.A0 : (z == 1) ? p.A1 : (z == 2) ? p.A2 : p.A3;
    float*       C = (z == 0) ? p.C0 : (z == 1) ? p.C1 : (z == 2) ? p.C2 : p.C3;
    const float* B = Wbase + (size_t)z * C_ * C_;
    tc_gemm_body(A, B, C, N, K, blockIdx.y * 128, blockIdx.x * 128, z == 3, smp);
}

// ---------------- fused mix: 5 outputs in one pass ----------------
__global__ __launch_bounds__(256) void mix_fused(
    const float* __restrict__ M1,
    const float* __restrict__ W2,
    const float* __restrict__ x, const float* __restrict__ SX,
    const float* __restrict__ wmaa, const float* __restrict__ kmaa,
    const float* __restrict__ vmaa, const float* __restrict__ rmaa,
    const float* __restrict__ gmaa,
    float* __restrict__ WX, float* __restrict__ KX, float* __restrict__ VX,
    float* __restrict__ RX, float* __restrict__ GX)
{
    __shared__ float M1s[64][33];
    __shared__ float W2s[32][68];
    int tid = threadIdx.x;
    int m0 = blockIdx.y * 64, n0 = blockIdx.x * 64;
    int tx = tid & 15, ty = tid >> 4;

    float4 xr[4], sxr[4];
    #pragma unroll
    for (int i = 0; i < 4; i++) {
        size_t idx = (size_t)(m0 + ty * 4 + i) * C_ + n0 + tx * 4;
        xr[i]  = *(const float4*)(x + idx);
        sxr[i] = *(const float4*)(SX + idx);
    }

    const float* maap[5] = {wmaa, kmaa, vmaa, rmaa, gmaa};
    float* outp[5] = {WX, KX, VX, RX, GX};

    for (int f = 0; f < 5; f++) {
        #pragma unroll
        for (int i = 0; i < 2; i++) {
            int c = tid + i * 256;
            int r = c >> 3, cc = (c & 7) << 2;
            float4 v4 = *(const float4*)(M1 + (size_t)(m0 + r) * 160 + f * 32 + cc);
            M1s[r][cc] = v4.x; M1s[r][cc + 1] = v4.y; M1s[r][cc + 2] = v4.z; M1s[r][cc + 3] = v4.w;
        }
        #pragma unroll
        for (int i = 0; i < 2; i++) {
            int c = tid + i * 256;
            int r = c >> 4, cc = (c & 15) << 2;
            float4 v4 = *(const float4*)(W2 + (size_t)(f * 32 + r) * C_ + n0 + cc);
            W2s[r][cc] = v4.x; W2s[r][cc + 1] = v4.y; W2s[r][cc + 2] = v4.z; W2s[r][cc + 3] = v4.w;
        }
        __syncthreads();

        float acc[4][4];
        #pragma unroll
        for (int i = 0; i < 4; i++)
            #pragma unroll
            for (int j = 0; j < 4; j++) acc[i][j] = 0.f;

        #pragma unroll
        for (int k = 0; k < 32; k++) {
            float a[4], b[4];
            #pragma unroll
            for (int i = 0; i < 4; i++) a[i] = M1s[ty * 4 + i][k];
            #pragma unroll
            for (int j = 0; j < 4; j++) b[j] = W2s[k][tx * 4 + j];
            #pragma unroll
            for (int i = 0; i < 4; i++)
                #pragma unroll
                for (int j = 0; j < 4; j++)
                    acc[i][j] = fmaf(a[i], b[j], acc[i][j]);
        }

        float4 mv = *(const float4*)(maap[f] + n0 + tx * 4);
        float* op = outp[f];
        bool rnd = (f >= 1);
        #pragma unroll
        for (int i = 0; i < 4; i++) {
            size_t idx = (size_t)(m0 + ty * 4 + i) * C_ + n0 + tx * 4;
            float4 o;
            const float* xi = (const float*)&xr[i];
            const float* si = (const float*)&sxr[i];
            const float* mi = (const float*)&mv;
            float* oo = (float*)&o;
            #pragma unroll
            for (int j = 0; j < 4; j++) {
                float v = fmaf(si[j], mi[j] + acc[i][j], xi[j]);
                oo[j] = rnd ? to_tf32(v) : v;
            }
            *(float4*)(op + idx) = o;
        }
        __syncthreads();
    }
}

// ---------------- chunked WKV scan ----------------
// phase 1: per-(bh,chunk) scan from zero state; writes partial Y, end state,
//          and the per-chunk decay product (w-writer threads accumulate it).
__global__ __launch_bounds__(256) void scanA(
    const float* __restrict__ R, const float* __restrict__ Kt,
    const float* __restrict__ V, const float* __restrict__ W,
    const float* __restrict__ u,
    float* __restrict__ Y, float* __restrict__ S, float* __restrict__ Dp)
{
    int blk = blockIdx.x;            // bh*NCH + ch
    int bh = blk >> 3, ch = blk & 7;
    int b = bh >> 4, h = bh & 15;
    int tid = threadIdx.x;
    int kq = tid >> 6, v = tid & 63;

    __shared__ float r_s[64], k_s[64], w_s[64], v_s[64];
    __shared__ float red[256];

    float u_r[16];
    #pragma unroll
    for (int i = 0; i < 16; i++) u_r[i] = u[h * 64 + kq * 16 + i];

    float st[16];
    #pragma unroll
    for (int i = 0; i < 16; i++) st[i] = 0.f;

    const size_t base = (size_t)b * T_ * C_ + (size_t)h * 64 + (size_t)(ch * TCH) * C_;
    const float* src = (tid < 64) ? R : (tid < 128) ? Kt : (tid < 192) ? W : V;
    int c = tid & 63;
    float pre = src[base + c];
    float prodw = 1.f;               // per-chunk decay product (w-writers only)

    for (int t = 0; t < TCH; ++t) {
        if (tid < 64)       r_s[c] = pre;
        else if (tid < 128) k_s[c] = pre;
        else if (tid < 192) { w_s[c] = pre; prodw *= pre; }
        else                v_s[c] = pre;
        __syncthreads();

        if (t < TCH - 1) pre = src[base + (size_t)(t + 1) * C_ + c];

        float vv = v_s[v];
        float y = 0.f;
        #pragma unroll
        for (int i = 0; i < 16; i++) {
            int kk = kq * 16 + i;
            float a = k_s[kk] * vv;
            y = fmaf(r_s[kk], fmaf(u_r[i], a, st[i]), y);
            st[i] = fmaf(w_s[kk], st[i], a);
        }
        red[tid] = y;
        __syncthreads();

        if (kq == 0) {
            float ys = ((red[v] + red[64 + v]) + (red[128 + v] + red[192 + v])) * 0.125f;
            Y[base + (size_t)t * C_ + v] = ys;
        }
    }

    float* Sp = S + (((size_t)blk * 64) + kq * 16) * 64 + v;
    #pragma unroll
    for (int i = 0; i < 16; i++) Sp[(size_t)i * 64] = st[i];

    if (tid >= 128 && tid < 192)
        Dp[blk * 64 + c] = prodw;
}

// phase 2: chunk-level recurrence in_{c+1} = D_c ⊙ in_c + S_c
__global__ __launch_bounds__(256) void scanB(
    const float* __restrict__ S, const float* __restrict__ Dp, float* __restrict__ SIn)
{
    int bh = blockIdx.x;
    int tid = threadIdx.x;
    int kq = tid >> 6, v = tid & 63;
    float in[16];
    #pragma unroll
    for (int i = 0; i < 16; i++) in[i] = 0.f;

    for (int cc = 0; cc < NCH - 1; cc++) {
        const float* Sp = S + (((size_t)(bh * NCH + cc) * 64) + kq * 16) * 64 + v;
        const float* Dq = Dp + (bh * NCH + cc) * 64 + kq * 16;
        float* Op = SIn + (((size_t)(bh * NCH + cc + 1) * 64) + kq * 16) * 64 + v;
        #pragma unroll
        for (int i = 0; i < 16; i++)
            in[i] = fmaf(Dq[i], in[i], Sp[(size_t)i * 64]);
        #pragma unroll
        for (int i = 0; i < 16; i++)
            Op[(size_t)i * 64] = in[i];
    }
}

// phase 3: homogeneous correction — y += r · (in ⊙ running decay)
__global__ __launch_bounds__(256) void scanC(
    const float* __restrict__ R, const float* __restrict__ W,
    const float* __restrict__ SIn, float* __restrict__ Y)
{
    int blk = blockIdx.x;            // bh*(NCH-1) + (ch-1)
    int bh = blk / (NCH - 1);
    int ch = blk % (NCH - 1) + 1;
    int b = bh >> 4, h = bh & 15;
    int tid = threadIdx.x;
    int kq = tid >> 6, v = tid & 63;

    __shared__ float r_s[64], w_s[64];
    __shared__ float red[256];

    float s2[16];
    const float* Ip = SIn + (((size_t)(bh * NCH + ch) * 64) + kq * 16) * 64 + v;
    #pragma unroll
    for (int i = 0; i < 16; i++) s2[i] = Ip[(size_t)i * 64];

    const size_t base = (size_t)b * T_ * C_ + (size_t)h * 64 + (size_t)(ch * TCH) * C_;
    float pre = 0.f;
    if (tid < 128) {
        const float* src = (tid < 64) ? R : W;
        pre = src[base + (tid & 63)];
    }

    for (int t = 0; t < TCH; ++t) {
        if (tid < 64)       r_s[tid] = pre;
        else if (tid < 128) w_s[tid - 64] = pre;
        __syncthreads();

        if (t < TCH - 1 && tid < 128) {
            const float* src = (tid < 64) ? R : W;
            pre = src[base + (size_t)(t + 1) * C_ + (tid & 63)];
        }

        float y = 0.f;
        #pragma unroll
        for (int i = 0; i < 16; i++) {
            int kk = kq * 16 + i;
            y = fmaf(r_s[kk], s2[i], y);
            s2[i] *= w_s[kk];
        }
        red[tid] = y;
        __syncthreads();

        if (kq == 0) {
            float ys = ((red[v] + red[64 + v]) + (red[128 + v] + red[192 + v])) * 0.125f;
            size_t yi = base + (size_t)t * C_ + v;
            Y[yi] += ys;
        }
    }
}

// ---------------- groupnorm + ln affine + gate (in-place on Y, tf32-rounded) ----------------
__global__ __launch_bounds__(256) void norm_gate(
    float* __restrict__ Y, const float* __restrict__ G,
    const float* __restrict__ lnw, const float* __restrict__ lnb)
{
    int wid = threadIdx.x >> 5;
    int lane = threadIdx.x & 31;
    int gi = blockIdx.x * 8 + wid;
    int m = gi >> 4, h = gi & 15;
    size_t p = (size_t)m * C_ + h * 64;

    float a = Y[p + lane], b2 = Y[p + 32 + lane];
    float s1 = a + b2;
    float s2 = a * a + b2 * b2;
    #pragma unroll
    for (int o = 16; o > 0; o >>= 1) {
        s1 += __shfl_xor_sync(0xffffffffu, s1, o);
        s2 += __shfl_xor_sync(0xffffffffu, s2, o);
    }
    float mean = s1 * (1.f / 64.f);
    float var  = s2 * (1.f / 64.f) - mean * mean;
    float rs = rsqrtf(var + 1e-5f);

    int c0 = h * 64 + lane;
    float o1 = fmaf((a  - mean) * rs, lnw[c0],      lnb[c0])      * G[p + lane];
    float o2 = fmaf((b2 - mean) * rs, lnw[c0 + 32], lnb[c0 + 32]) * G[p + 32 + lane];
    Y[p + lane]      = to_tf32(o1);
    Y[p + 32 + lane] = to_tf32(o2);
}

// ---------------- launch ----------------
extern "C" void kernel_launch(void* const* d_in, const int* in_sizes, int n_in,
                              void* d_out, int out_size)
{
    (void)in_sizes; (void)n_in; (void)out_size;
    const float* x          = (const float*)d_in[0];
    const float* x_maa      = (const float*)d_in[1];
    const float* w_maa      = (const float*)d_in[2];
    const float* k_maa      = (const float*)d_in[3];
    const float* v_maa      = (const float*)d_in[4];
    const float* r_maa      = (const float*)d_in[5];
    const float* g_maa      = (const float*)d_in[6];
    const float* tm_w1      = (const float*)d_in[7];
    const float* tm_w2      = (const float*)d_in[8];
    const float* td_w1      = (const float*)d_in[9];
    const float* td_w2      = (const float*)d_in[10];
    const float* time_decay = (const float*)d_in[11];
    const float* time_first = (const float*)d_in[12];
    const float* Wr         = (const float*)d_in[13];
    const float* Wk         = (const float*)d_in[14];
    const float* Wv         = (const float*)d_in[15];
    const float* Wg         = (const float*)d_in[16];
    const float* Wo         = (const float*)d_in[17];
    const float* ln_w       = (const float*)d_in[18];
    const float* ln_b       = (const float*)d_in[19];
    float* out = (float*)d_out;

    float *SX, *XS, *M1, *WX, *KX, *VX, *RX, *GX, *Rb, *Kb, *Vb, *Gb, *Wd, *WT, *Yb,
          *Wrn, *P1, *P2, *St, *SIn, *Dp;
    cudaGetSymbolAddress((void**)&SX, d_SX);
    cudaGetSymbolAddress((void**)&XS, d_XS);
    cudaGetSymbolAddress((void**)&M1, d_M1);
    cudaGetSymbolAddress((void**)&WX, d_WX);
    cudaGetSymbolAddress((void**)&KX, d_KX);
    cudaGetSymbolAddress((void**)&VX, d_VX);
    cudaGetSymbolAddress((void**)&RX, d_RX);
    cudaGetSymbolAddress((void**)&GX, d_GX);
    cudaGetSymbolAddress((void**)&Rb, d_R);
    cudaGetSymbolAddress((void**)&Kb, d_K);
    cudaGetSymbolAddress((void**)&Vb, d_V);
    cudaGetSymbolAddress((void**)&Gb, d_G);
    cudaGetSymbolAddress((void**)&Wd, d_Wd);
    cudaGetSymbolAddress((void**)&WT, d_WT);
    cudaGetSymbolAddress((void**)&Yb, d_Y);
    cudaGetSymbolAddress((void**)&Wrn, d_Wrnd);
    cudaGetSymbolAddress((void**)&P1, d_P1);
    cudaGetSymbolAddress((void**)&P2, d_P2);
    cudaGetSymbolAddress((void**)&St, d_State);
    cudaGetSymbolAddress((void**)&SIn, d_SIn);
    cudaGetSymbolAddress((void**)&Dp, d_Dp);

    const int tc_smem = TC_SMEM_FLOATS * (int)sizeof(float);
    cudaFuncSetAttribute(tc_gemm,    cudaFuncAttributeMaxDynamicSharedMemorySize, tc_smem);
    cudaFuncSetAttribute(tc_gemm_b4, cudaFuncAttributeMaxDynamicSharedMemorySize, tc_smem);

    dim3 blk(256);

    // 0. tf32-round weights: order r,k,v,g,o
    round5<<<dim3(C_ * C_ / 4 / 256, 5), blk>>>(Wr, Wk, Wv, Wg, Wo, Wrn);

    // 1. prep
    prep_kernel<<<(NTOK * C_ / 4 + 255) / 256, blk>>>(x, x_maa, SX, XS);

    // 2. M1 = tanh(XS @ tm_w1)   [4096,160]  (split-K)
    splitk_gemm<<<dim3(3, 32, KS_), blk>>>(XS, C_, tm_w1, P1, NTOK, 160, C_);
    reduce_tanh<<<(NTOK * 160 + 255) / 256, blk>>>(P1, M1, NTOK * 160);

    // 3. fused mix -> WX,KX,VX,RX,GX
    mix_fused<<<dim3(16, 64), blk>>>(M1, tm_w2, x, SX,
                                     w_maa, k_maa, v_maa, r_maa, g_maa,
                                     WX, KX, VX, RX, GX);

    // 4. projections: batched R,K,V,G (G=silu)
    Batch4 bp { RX, KX, VX, GX, Rb, Kb, Vb, Gb };
    tc_gemm_b4<<<dim3(8, 32, 4), blk, tc_smem>>>(bp, Wrn, NTOK, C_, C_);

    // 5. decay LoRA: WT = tanh(WX @ td_w1) (split-K); Wd = exp(-exp(td + WT @ td_w2))
    splitk_gemm<<<dim3(1, 32, KS_), blk>>>(WX, C_, td_w1, P2, NTOK, 64, C_);
    reduce_tanh<<<(NTOK * 64 + 255) / 256, blk>>>(P2, WT, NTOK * 64);
    gemm_decay<<<dim3(8, 32), blk>>>(WT, 64, td_w2, Wd, NTOK, C_, 64, time_decay);

    // 6. chunked WKV scan (Dp fused into scanA), then groupnorm+gate
    scanA<<<64 * NCH, blk>>>(Rb, Kb, Vb, Wd, time_first, Yb, St, Dp);
    scanB<<<64, blk>>>(St, Dp, SIn);
    scanC<<<64 * (NCH - 1), blk>>>(Rb, Wd, SIn, Yb);
    norm_gate<<<NTOK * H_ / 8, blk>>>(Yb, Gb, ln_w, ln_b);

    // 7. output projection
    tc_gemm<<<dim3(8, 32), blk, tc_smem>>>(Yb, Wrn + 4 * (size_t)C_ * C_, out, NTOK, C_, C_);
}

// round 9
// speedup vs baseline: 3.6733x; 1.7420x over previous
#include <cuda_runtime.h>
#include <cuda_fp16.h>
#include <mma.h>
#include <math.h>
#include <stdint.h>

using namespace nvcuda;

#define B_ 4
#define T_ 1024
#define C_ 1024
#define H_ 16
#define NTOK (B_*T_)
#define KS_ 4     // split-K factor for skinny GEMMs
#define NCH 8     // scan chunks
#define TCH 128   // steps per chunk

// ---------------- scratch (device globals; no allocation allowed) ----------------
__device__ float d_SX[NTOK*C_];
__device__ float d_XS[NTOK*C_];
__device__ float d_M1[NTOK*160];
__device__ float d_WX[NTOK*C_];
__device__ __half d_KXh[NTOK*C_];
__device__ __half d_VXh[NTOK*C_];
__device__ __half d_RXh[NTOK*C_];
__device__ __half d_GXh[NTOK*C_];
__device__ float d_R [NTOK*C_];
__device__ float d_K [NTOK*C_];
__device__ float d_V [NTOK*C_];
__device__ float d_G [NTOK*C_];
__device__ float d_Wd[NTOK*C_];
__device__ float d_WT[NTOK*64];
__device__ float d_Y [NTOK*C_];
__device__ __half d_Yh[NTOK*C_];
__device__ __half d_Wh[5*C_*C_];           // 5 fp16 weights [K,N]
__device__ float d_P1[KS_*NTOK*160];       // split-K partials (tm)
__device__ float d_P2[KS_*NTOK*64];        // split-K partials (td)
__device__ float d_State[64*NCH*64*64];    // per-(bh,chunk) end state [k][v]
__device__ float d_SIn  [64*NCH*64*64];    // per-(bh,chunk) entry state
__device__ float d_Dp   [64*NCH*64];       // per-(bh,chunk) decay product [k]

// ---------------- helpers ----------------
__device__ __forceinline__ void cp_async16(uint32_t dst, const void* src) {
    asm volatile("cp.async.cg.shared.global [%0], [%1], 16;\n" :: "r"(dst), "l"(src));
}
__device__ __forceinline__ void cp_commit() { asm volatile("cp.async.commit_group;\n"); }
template<int N> __device__ __forceinline__ void cp_wait() {
    asm volatile("cp.async.wait_group %0;\n" :: "n"(N));
}

// pack 4 floats -> 4 halves (8B)
__device__ __forceinline__ uint2 f4_to_h4(float a, float b, float c, float d) {
    __half2 lo = __floats2half2_rn(a, b);
    __half2 hi = __floats2half2_rn(c, d);
    uint2 r;
    r.x = *(uint32_t*)&lo;
    r.y = *(uint32_t*)&hi;
    return r;
}

// ---------------- prep ----------------
__global__ void prep_kernel(const float* __restrict__ x, const float* __restrict__ xmaa,
                            float* __restrict__ SX, float* __restrict__ XS)
{
    int i4 = blockIdx.x * blockDim.x + threadIdx.x;
    int i  = i4 * 4;
    if (i >= NTOK * C_) return;
    int m = i >> 10;
    int c = i & 1023;
    int t = m & (T_ - 1);
    float4 xv = *(const float4*)(x + i);
    float4 xp = make_float4(0.f, 0.f, 0.f, 0.f);
    if (t != 0) xp = *(const float4*)(x + i - C_);
    float4 ma = *(const float4*)(xmaa + c);
    float4 sx, xs;
    sx.x = xp.x - xv.x; sx.y = xp.y - xv.y; sx.z = xp.z - xv.z; sx.w = xp.w - xv.w;
    xs.x = fmaf(sx.x, ma.x, xv.x); xs.y = fmaf(sx.y, ma.y, xv.y);
    xs.z = fmaf(sx.z, ma.z, xv.z); xs.w = fmaf(sx.w, ma.w, xv.w);
    *(float4*)(SX + i) = sx;
    *(float4*)(XS + i) = xs;
}

// ---------------- convert 5 weights to fp16 (layout preserved [K,N]) ----------------
__global__ void cvt5(const float* __restrict__ W0, const float* __restrict__ W1,
                     const float* __restrict__ W2, const float* __restrict__ W3,
                     const float* __restrict__ W4, __half* __restrict__ out)
{
    const float* srcs[5] = {W0, W1, W2, W3, W4};
    int i = (blockIdx.x * blockDim.x + threadIdx.x) * 4;
    int which = blockIdx.y;
    const float* src = srcs[which];
    __half* dst = out + (size_t)which * C_ * C_;
    float4 v = *(const float4*)(src + i);
    *(uint2*)(dst + i) = f4_to_h4(v.x, v.y, v.z, v.w);
}

// ---------------- split-K fp32 GEMM for skinny N ----------------
__global__ __launch_bounds__(256) void splitk_gemm(
    const float* __restrict__ A, int lda,
    const float* __restrict__ B,
    float* __restrict__ P,
    int M, int N, int K)
{
    const int BM = 128, BN = 64, BK = 16;
    __shared__ float As[BK][BM + 4];
    __shared__ float Bs[BK][BN + 4];
    int tid = threadIdx.x;
    int n0 = blockIdx.x * BN;
    int m0 = blockIdx.y * BM;
    int KC = K / gridDim.z;
    int kbeg = blockIdx.z * KC;

    int arow = tid >> 2;
    int acol = (tid & 3) << 2;
    int brow = tid >> 4;
    int bcol = (tid & 15) << 2;
    int tx = tid & 15, ty = tid >> 4;

    float acc[8][4];
    #pragma unroll
    for (int i = 0; i < 8; i++)
        #pragma unroll
        for (int j = 0; j < 4; j++) acc[i][j] = 0.f;

    for (int k0 = kbeg; k0 < kbeg + KC; k0 += BK) {
        #pragma unroll
        for (int i = 0; i < 2; i++) {
            int r = arow + i * 64;
            const float4 av = *(const float4*)(A + (size_t)(m0 + r) * lda + (k0 + acol));
            As[acol + 0][r] = av.x; As[acol + 1][r] = av.y;
            As[acol + 2][r] = av.z; As[acol + 3][r] = av.w;
        }
        {
            float4 bv = make_float4(0.f, 0.f, 0.f, 0.f);
            if (n0 + bcol < N)
                bv = *(const float4*)(B + (size_t)(k0 + brow) * N + (n0 + bcol));
            *(float4*)&Bs[brow][bcol] = bv;
        }
        __syncthreads();
        #pragma unroll
        for (int kk = 0; kk < BK; kk++) {
            float a[8], b[4];
            *(float4*)&a[0] = *(const float4*)&As[kk][ty * 8];
            *(float4*)&a[4] = *(const float4*)&As[kk][ty * 8 + 4];
            *(float4*)&b[0] = *(const float4*)&Bs[kk][tx * 4];
            #pragma unroll
            for (int i = 0; i < 8; i++)
                #pragma unroll
                for (int j = 0; j < 4; j++)
                    acc[i][j] = fmaf(a[i], b[j], acc[i][j]);
        }
        __syncthreads();
    }

    float* Pz = P + (size_t)blockIdx.z * M * N;
    #pragma unroll
    for (int i = 0; i < 8; i++) {
        int m = m0 + ty * 8 + i;
        int n = n0 + tx * 4;
        if (n < N)
            *(float4*)(Pz + (size_t)m * N + n) = *(float4*)&acc[i][0];
    }
}

// ---------------- reduce split-K partials + tanh ----------------
__global__ void reduce_tanh(const float* __restrict__ P, float* __restrict__ out, int MN)
{
    int i = blockIdx.x * blockDim.x + threadIdx.x;
    if (i >= MN) return;
    float s = 0.f;
    #pragma unroll
    for (int z = 0; z < KS_; z++) s += P[(size_t)z * MN + i];
    out[i] = tanhf(s);
}

// ---------------- fp32 GEMM with decay epilogue (K=64) ----------------
__global__ __launch_bounds__(256) void gemm_decay(
    const float* __restrict__ A, int lda,
    const float* __restrict__ B,
    float* __restrict__ C,
    int M, int N, int K,
    const float* __restrict__ e2)
{
    const int BM = 128, BN = 128, BK = 16;
    __shared__ float As[BK][BM + 4];
    __shared__ float Bs[BK][BN + 4];
    int tid = threadIdx.x;
    int m0 = blockIdx.y * BM;
    int n0 = blockIdx.x * BN;
    int tx = tid & 15, ty = tid >> 4;

    int arow = tid >> 2;
    int acol = (tid & 3) << 2;
    int brow = tid >> 5;
    int bcol = (tid & 31) << 2;

    float acc[8][8];
    #pragma unroll
    for (int i = 0; i < 8; i++)
        #pragma unroll
        for (int j = 0; j < 8; j++) acc[i][j] = 0.f;

    for (int k0 = 0; k0 < K; k0 += BK) {
        #pragma unroll
        for (int i = 0; i < 2; i++) {
            int r = arow + i * 64;
            const float4 av = *(const float4*)(A + (size_t)(m0 + r) * lda + (k0 + acol));
            As[acol + 0][r] = av.x; As[acol + 1][r] = av.y;
            As[acol + 2][r] = av.z; As[acol + 3][r] = av.w;
        }
        #pragma unroll
        for (int i = 0; i < 2; i++) {
            int r = brow + i * 8;
            float4 bv = *(const float4*)(B + (size_t)(k0 + r) * N + (n0 + bcol));
            *(float4*)&Bs[r][bcol] = bv;
        }
        __syncthreads();
        #pragma unroll
        for (int kk = 0; kk < BK; kk++) {
            float a[8], b[8];
            *(float4*)&a[0] = *(const float4*)&As[kk][ty * 8];
            *(float4*)&a[4] = *(const float4*)&As[kk][ty * 8 + 4];
            *(float4*)&b[0] = *(const float4*)&Bs[kk][tx * 8];
            *(float4*)&b[4] = *(const float4*)&Bs[kk][tx * 8 + 4];
            #pragma unroll
            for (int i = 0; i < 8; i++)
                #pragma unroll
                for (int j = 0; j < 8; j++)
                    acc[i][j] = fmaf(a[i], b[j], acc[i][j]);
        }
        __syncthreads();
    }

    #pragma unroll
    for (int i = 0; i < 8; i++) {
        int m = m0 + ty * 8 + i;
        #pragma unroll
        for (int j = 0; j < 8; j++) {
            int n = n0 + tx * 8 + j;
            C[(size_t)m * N + n] = expf(-expf(e2[n] + acc[i][j]));
        }
    }
}

// ---------------- pipelined fp16 wmma GEMM core (BK=64, 3 stages, 2 CTAs/SM) ----------------
#define TG_STAGES 3
#define TG_BK 64
#define TG_ALD 72      // 64 k-halves + 8 pad (16B)
#define TG_BLD 136     // 128 n-halves + 8 pad
#define TG_SMEM_HALVES (TG_STAGES * (128 * TG_ALD + TG_BK * TG_BLD))

__device__ __forceinline__ void tc_gemm_h_body(
    const __half* __restrict__ A, const __half* __restrict__ B, float* __restrict__ C,
    int N, int K, int m0, int n0, bool silu, __half* smp)
{
    __half* As = smp;                              // [S][128][72]
    __half* Bs = smp + TG_STAGES * 128 * TG_ALD;   // [S][64][136]

    int tid = threadIdx.x;
    int wid = tid >> 5;
    int lane = tid & 31;
    int wm = wid >> 2;   // 0..1  (64-row slab)
    int wn = wid & 3;    // 0..3  (32-col slab)

    wmma::fragment<wmma::accumulator, 16, 16, 16, float> acc[4][2];
    #pragma unroll
    for (int i = 0; i < 4; i++)
        #pragma unroll
        for (int j = 0; j < 2; j++) wmma::fill_fragment(acc[i][j], 0.f);

    const int KT = K >> 6;   // BK=64

    auto load_tile = [&](int t, int s) {
        int k0 = t << 6;
        #pragma unroll
        for (int i = 0; i < 4; i++) {           // A: 128 rows x 64 halves (16KB)
            int c = tid + i * 256;
            int row = c >> 3;
            int kc  = (c & 7) << 3;             // 8 halves per 16B chunk
            uint32_t dst = (uint32_t)__cvta_generic_to_shared(
                As + ((size_t)(s * 128 + row)) * TG_ALD + kc);
            cp_async16(dst, A + (size_t)(m0 + row) * K + (k0 + kc));
        }
        #pragma unroll
        for (int i = 0; i < 4; i++) {           // B: 64 rows x 128 halves (16KB)
            int c = tid + i * 256;
            int kr = c >> 4;
            int nc = (c & 15) << 3;
            uint32_t dst = (uint32_t)__cvta_generic_to_shared(
                Bs + ((size_t)(s * TG_BK + kr)) * TG_BLD + nc);
            cp_async16(dst, B + (size_t)(k0 + kr) * N + (n0 + nc));
        }
    };

    load_tile(0, 0); cp_commit();
    load_tile(1, 1); cp_commit();

    for (int t = 0; t < KT; ++t) {
        int s = t % TG_STAGES;
        cp_wait<1>();
        __syncthreads();
        int pt = t + 2;
        if (pt < KT) load_tile(pt, pt % TG_STAGES);
        cp_commit();

        #pragma unroll
        for (int kk = 0; kk < TG_BK; kk += 16) {
            wmma::fragment<wmma::matrix_a, 16, 16, 16, half, wmma::row_major> af[4];
            wmma::fragment<wmma::matrix_b, 16, 16, 16, half, wmma::row_major> bf[2];
            #pragma unroll
            for (int i = 0; i < 4; i++)
                wmma::load_matrix_sync(af[i], As + ((size_t)(s * 128 + wm * 64 + i * 16)) * TG_ALD + kk, TG_ALD);
            #pragma unroll
            for (int j = 0; j < 2; j++)
                wmma::load_matrix_sync(bf[j], Bs + ((size_t)(s * TG_BK + kk)) * TG_BLD + wn * 32 + j * 16, TG_BLD);
            #pragma unroll
            for (int i = 0; i < 4; i++)
                #pragma unroll
                for (int j = 0; j < 2; j++)
                    wmma::mma_sync(acc[i][j], af[i], bf[j], acc[i][j]);
        }
    }
    cp_wait<0>();
    __syncthreads();

    float* stg = (float*)(smp) + wid * 16 * 20;   // per-warp staging (reuses As region)

    #pragma unroll
    for (int i = 0; i < 4; i++) {
        #pragma unroll
        for (int j = 0; j < 2; j++) {
            int mb = m0 + wm * 64 + i * 16;
            int nb = n0 + wn * 32 + j * 16;
            if (!silu) {
                wmma::store_matrix_sync(C + (size_t)mb * N + nb, acc[i][j], N, wmma::mem_row_major);
            } else {
                wmma::store_matrix_sync(stg, acc[i][j], 20, wmma::mem_row_major);
                __syncwarp();
                int r  = lane >> 1;
                int c0 = (lane & 1) * 8;
                #pragma unroll
                for (int q = 0; q < 8; q++) {
                    float v = stg[r * 20 + c0 + q];
                    C[(size_t)(mb + r) * N + (nb + c0 + q)] = v / (1.f + expf(-v));
                }
                __syncwarp();
            }
        }
    }
}

// single GEMM (Wo)
__global__ __launch_bounds__(256, 2) void tc_gemm_h(
    const __half* __restrict__ A, const __half* __restrict__ B,
    float* __restrict__ C, int M, int N, int K)
{
    extern __shared__ __half smph[];
    tc_gemm_h_body(A, B, C, N, K, blockIdx.y * 128, blockIdx.x * 128, false, smph);
}

// z-batched 4 projections (R,K,V,G) — G gets silu
struct Batch4h {
    const __half *A0, *A1, *A2, *A3;
    float *C0, *C1, *C2, *C3;
};
__global__ __launch_bounds__(256, 2) void tc_gemm_h_b4(
    Batch4h p, const __half* __restrict__ Wbase, int M, int N, int K)
{
    extern __shared__ __half smph[];
    int z = blockIdx.z;
    const __half* A = (z == 0) ? p.A0 : (z == 1) ? p.A1 : (z == 2) ? p.A2 : p.A3;
    float*        C = (z == 0) ? p.C0 : (z == 1) ? p.C1 : (z == 2) ? p.C2 : p.C3;
    const __half* B = Wbase + (size_t)z * C_ * C_;
    tc_gemm_h_body(A, B, C, N, K, blockIdx.y * 128, blockIdx.x * 128, z == 3, smph);
}

// ---------------- fused mix: 5 outputs in one pass ----------------
// f=0 (w-mix) -> fp32 WX (feeds fp32 LoRA GEMM); f>=1 -> fp16 (feed fp16 tensor GEMMs)
__global__ __launch_bounds__(256) void mix_fused(
    const float* __restrict__ M1,
    const float* __restrict__ W2,
    const float* __restrict__ x, const float* __restrict__ SX,
    const float* __restrict__ wmaa, const float* __restrict__ kmaa,
    const float* __restrict__ vmaa, const float* __restrict__ rmaa,
    const float* __restrict__ gmaa,
    float* __restrict__ WX, __half* __restrict__ KXh, __half* __restrict__ VXh,
    __half* __restrict__ RXh, __half* __restrict__ GXh)
{
    __shared__ float M1s[64][33];
    __shared__ float W2s[32][68];
    int tid = threadIdx.x;
    int m0 = blockIdx.y * 64, n0 = blockIdx.x * 64;
    int tx = tid & 15, ty = tid >> 4;

    float4 xr[4], sxr[4];
    #pragma unroll
    for (int i = 0; i < 4; i++) {
        size_t idx = (size_t)(m0 + ty * 4 + i) * C_ + n0 + tx * 4;
        xr[i]  = *(const float4*)(x + idx);
        sxr[i] = *(const float4*)(SX + idx);
    }

    const float* maap[5] = {wmaa, kmaa, vmaa, rmaa, gmaa};
    __half* outh[5] = {nullptr, KXh, VXh, RXh, GXh};

    for (int f = 0; f < 5; f++) {
        #pragma unroll
        for (int i = 0; i < 2; i++) {
            int c = tid + i * 256;
            int r = c >> 3, cc = (c & 7) << 2;
            float4 v4 = *(const float4*)(M1 + (size_t)(m0 + r) * 160 + f * 32 + cc);
            M1s[r][cc] = v4.x; M1s[r][cc + 1] = v4.y; M1s[r][cc + 2] = v4.z; M1s[r][cc + 3] = v4.w;
        }
        #pragma unroll
        for (int i = 0; i < 2; i++) {
            int c = tid + i * 256;
            int r = c >> 4, cc = (c & 15) << 2;
            float4 v4 = *(const float4*)(W2 + (size_t)(f * 32 + r) * C_ + n0 + cc);
            W2s[r][cc] = v4.x; W2s[r][cc + 1] = v4.y; W2s[r][cc + 2] = v4.z; W2s[r][cc + 3] = v4.w;
        }
        __syncthreads();

        float acc[4][4];
        #pragma unroll
        for (int i = 0; i < 4; i++)
            #pragma unroll
            for (int j = 0; j < 4; j++) acc[i][j] = 0.f;

        #pragma unroll
        for (int k = 0; k < 32; k++) {
            float a[4], b[4];
            #pragma unroll
            for (int i = 0; i < 4; i++) a[i] = M1s[ty * 4 + i][k];
            #pragma unroll
            for (int j = 0; j < 4; j++) b[j] = W2s[k][tx * 4 + j];
            #pragma unroll
            for (int i = 0; i < 4; i++)
                #pragma unroll
                for (int j = 0; j < 4; j++)
                    acc[i][j] = fmaf(a[i], b[j], acc[i][j]);
        }

        float4 mv = *(const float4*)(maap[f] + n0 + tx * 4);
        #pragma unroll
        for (int i = 0; i < 4; i++) {
            size_t idx = (size_t)(m0 + ty * 4 + i) * C_ + n0 + tx * 4;
            float o0 = fmaf(sxr[i].x, mv.x + acc[i][0], xr[i].x);
            float o1 = fmaf(sxr[i].y, mv.y + acc[i][1], xr[i].y);
            float o2 = fmaf(sxr[i].z, mv.z + acc[i][2], xr[i].z);
            float o3 = fmaf(sxr[i].w, mv.w + acc[i][3], xr[i].w);
            if (f == 0) {
                float4 o = make_float4(o0, o1, o2, o3);
                *(float4*)(WX + idx) = o;
            } else {
                *(uint2*)(outh[f] + idx) = f4_to_h4(o0, o1, o2, o3);
            }
        }
        __syncthreads();
    }
}

// ---------------- chunked WKV scan ----------------
// phase 1: per-(bh,chunk) scan from zero state; writes partial Y, end state,
//          and the per-chunk decay product (w-writer threads accumulate it).
__global__ __launch_bounds__(256) void scanA(
    const float* __restrict__ R, const float* __restrict__ Kt,
    const float* __restrict__ V, const float* __restrict__ W,
    const float* __restrict__ u,
    float* __restrict__ Y, float* __restrict__ S, float* __restrict__ Dp)
{
    int blk = blockIdx.x;            // bh*NCH + ch
    int bh = blk >> 3, ch = blk & 7;
    int b = bh >> 4, h = bh & 15;
    int tid = threadIdx.x;
    int kq = tid >> 6, v = tid & 63;

    __shared__ float r_s[64], k_s[64], w_s[64], v_s[64];
    __shared__ float red[256];

    float u_r[16];
    #pragma unroll
    for (int i = 0; i < 16; i++) u_r[i] = u[h * 64 + kq * 16 + i];

    float st[16];
    #pragma unroll
    for (int i = 0; i < 16; i++) st[i] = 0.f;

    const size_t base = (size_t)b * T_ * C_ + (size_t)h * 64 + (size_t)(ch * TCH) * C_;
    const float* src = (tid < 64) ? R : (tid < 128) ? Kt : (tid < 192) ? W : V;
    int c = tid & 63;
    float pre = src[base + c];
    float prodw = 1.f;

    for (int t = 0; t < TCH; ++t) {
        if (tid < 64)       r_s[c] = pre;
        else if (tid < 128) k_s[c] = pre;
        else if (tid < 192) { w_s[c] = pre; prodw *= pre; }
        else                v_s[c] = pre;
        __syncthreads();

        if (t < TCH - 1) pre = src[base + (size_t)(t + 1) * C_ + c];

        float vv = v_s[v];
        float y = 0.f;
        #pragma unroll
        for (int i = 0; i < 16; i++) {
            int kk = kq * 16 + i;
            float a = k_s[kk] * vv;
            y = fmaf(r_s[kk], fmaf(u_r[i], a, st[i]), y);
            st[i] = fmaf(w_s[kk], st[i], a);
        }
        red[tid] = y;
        __syncthreads();

        if (kq == 0) {
            float ys = ((red[v] + red[64 + v]) + (red[128 + v] + red[192 + v])) * 0.125f;
            Y[base + (size_t)t * C_ + v] = ys;
        }
    }

    float* Sp = S + (((size_t)blk * 64) + kq * 16) * 64 + v;
    #pragma unroll
    for (int i = 0; i < 16; i++) Sp[(size_t)i * 64] = st[i];

    if (tid >= 128 && tid < 192)
        Dp[blk * 64 + c] = prodw;
}

// phase 2: chunk-level recurrence in_{c+1} = D_c ⊙ in_c + S_c
__global__ __launch_bounds__(256) void scanB(
    const float* __restrict__ S, const float* __restrict__ Dp, float* __restrict__ SIn)
{
    int bh = blockIdx.x;
    int tid = threadIdx.x;
    int kq = tid >> 6, v = tid & 63;
    float in[16];
    #pragma unroll
    for (int i = 0; i < 16; i++) in[i] = 0.f;

    for (int cc = 0; cc < NCH - 1; cc++) {
        const float* Sp = S + (((size_t)(bh * NCH + cc) * 64) + kq * 16) * 64 + v;
        const float* Dq = Dp + (bh * NCH + cc) * 64 + kq * 16;
        float* Op = SIn + (((size_t)(bh * NCH + cc + 1) * 64) + kq * 16) * 64 + v;
        #pragma unroll
        for (int i = 0; i < 16; i++)
            in[i] = fmaf(Dq[i], in[i], Sp[(size_t)i * 64]);
        #pragma unroll
        for (int i = 0; i < 16; i++)
            Op[(size_t)i * 64] = in[i];
    }
}

// phase 3: homogeneous correction — y += r · (in ⊙ running decay)
__global__ __launch_bounds__(256) void scanC(
    const float* __restrict__ R, const float* __restrict__ W,
    const float* __restrict__ SIn, float* __restrict__ Y)
{
    int blk = blockIdx.x;            // bh*(NCH-1) + (ch-1)
    int bh = blk / (NCH - 1);
    int ch = blk % (NCH - 1) + 1;
    int b = bh >> 4, h = bh & 15;
    int tid = threadIdx.x;
    int kq = tid >> 6, v = tid & 63;

    __shared__ float r_s[64], w_s[64];
    __shared__ float red[256];

    float s2[16];
    const float* Ip = SIn + (((size_t)(bh * NCH + ch) * 64) + kq * 16) * 64 + v;
    #pragma unroll
    for (int i = 0; i < 16; i++) s2[i] = Ip[(size_t)i * 64];

    const size_t base = (size_t)b * T_ * C_ + (size_t)h * 64 + (size_t)(ch * TCH) * C_;
    float pre = 0.f;
    if (tid < 128) {
        const float* src = (tid < 64) ? R : W;
        pre = src[base + (tid & 63)];
    }

    for (int t = 0; t < TCH; ++t) {
        if (tid < 64)       r_s[tid] = pre;
        else if (tid < 128) w_s[tid - 64] = pre;
        __syncthreads();

        if (t < TCH - 1 && tid < 128) {
            const float* src = (tid < 64) ? R : W;
            pre = src[base + (size_t)(t + 1) * C_ + (tid & 63)];
        }

        float y = 0.f;
        #pragma unroll
        for (int i = 0; i < 16; i++) {
            int kk = kq * 16 + i;
            y = fmaf(r_s[kk], s2[i], y);
            s2[i] *= w_s[kk];
        }
        red[tid] = y;
        __syncthreads();

        if (kq == 0) {
            float ys = ((red[v] + red[64 + v]) + (red[128 + v] + red[192 + v])) * 0.125f;
            size_t yi = base + (size_t)t * C_ + v;
            Y[yi] += ys;
        }
    }
}

// ---------------- groupnorm + ln affine + gate -> fp16 Y ----------------
__global__ __launch_bounds__(256) void norm_gate(
    const float* __restrict__ Y, const float* __restrict__ G,
    const float* __restrict__ lnw, const float* __restrict__ lnb,
    __half* __restrict__ Yh)
{
    int wid = threadIdx.x >> 5;
    int lane = threadIdx.x & 31;
    int gi = blockIdx.x * 8 + wid;
    int m = gi >> 4, h = gi & 15;
    size_t p = (size_t)m * C_ + h * 64;

    float a = Y[p + lane], b2 = Y[p + 32 + lane];
    float s1 = a + b2;
    float s2 = a * a + b2 * b2;
    #pragma unroll
    for (int o = 16; o > 0; o >>= 1) {
        s1 += __shfl_xor_sync(0xffffffffu, s1, o);
        s2 += __shfl_xor_sync(0xffffffffu, s2, o);
    }
    float mean = s1 * (1.f / 64.f);
    float var  = s2 * (1.f / 64.f) - mean * mean;
    float rs = rsqrtf(var + 1e-5f);

    int c0 = h * 64 + lane;
    float o1 = fmaf((a  - mean) * rs, lnw[c0],      lnb[c0])      * G[p + lane];
    float o2 = fmaf((b2 - mean) * rs, lnw[c0 + 32], lnb[c0 + 32]) * G[p + 32 + lane];
    Yh[p + lane]      = __float2half_rn(o1);
    Yh[p + 32 + lane] = __float2half_rn(o2);
}

// ---------------- launch ----------------
extern "C" void kernel_launch(void* const* d_in, const int* in_sizes, int n_in,
                              void* d_out, int out_size)
{
    (void)in_sizes; (void)n_in; (void)out_size;
    const float* x          = (const float*)d_in[0];
    const float* x_maa      = (const float*)d_in[1];
    const float* w_maa      = (const float*)d_in[2];
    const float* k_maa      = (const float*)d_in[3];
    const float* v_maa      = (const float*)d_in[4];
    const float* r_maa      = (const float*)d_in[5];
    const float* g_maa      = (const float*)d_in[6];
    const float* tm_w1      = (const float*)d_in[7];
    const float* tm_w2      = (const float*)d_in[8];
    const float* td_w1      = (const float*)d_in[9];
    const float* td_w2      = (const float*)d_in[10];
    const float* time_decay = (const float*)d_in[11];
    const float* time_first = (const float*)d_in[12];
    const float* Wr         = (const float*)d_in[13];
    const float* Wk         = (const float*)d_in[14];
    const float* Wv         = (const float*)d_in[15];
    const float* Wg         = (const float*)d_in[16];
    const float* Wo         = (const float*)d_in[17];
    const float* ln_w       = (const float*)d_in[18];
    const float* ln_b       = (const float*)d_in[19];
    float* out = (float*)d_out;

    float *SX, *XS, *M1, *WX, *Rb, *Kb, *Vb, *Gb, *Wd, *WT, *Yb, *P1, *P2, *St, *SIn, *Dp;
    __half *KXh, *VXh, *RXh, *GXh, *Yh, *Wh;
    cudaGetSymbolAddress((void**)&SX, d_SX);
    cudaGetSymbolAddress((void**)&XS, d_XS);
    cudaGetSymbolAddress((void**)&M1, d_M1);
    cudaGetSymbolAddress((void**)&WX, d_WX);
    cudaGetSymbolAddress((void**)&KXh, d_KXh);
    cudaGetSymbolAddress((void**)&VXh, d_VXh);
    cudaGetSymbolAddress((void**)&RXh, d_RXh);
    cudaGetSymbolAddress((void**)&GXh, d_GXh);
    cudaGetSymbolAddress((void**)&Rb, d_R);
    cudaGetSymbolAddress((void**)&Kb, d_K);
    cudaGetSymbolAddress((void**)&Vb, d_V);
    cudaGetSymbolAddress((void**)&Gb, d_G);
    cudaGetSymbolAddress((void**)&Wd, d_Wd);
    cudaGetSymbolAddress((void**)&WT, d_WT);
    cudaGetSymbolAddress((void**)&Yb, d_Y);
    cudaGetSymbolAddress((void**)&Yh, d_Yh);
    cudaGetSymbolAddress((void**)&Wh, d_Wh);
    cudaGetSymbolAddress((void**)&P1, d_P1);
    cudaGetSymbolAddress((void**)&P2, d_P2);
    cudaGetSymbolAddress((void**)&St, d_State);
    cudaGetSymbolAddress((void**)&SIn, d_SIn);
    cudaGetSymbolAddress((void**)&Dp, d_Dp);

    const int tg_smem = TG_SMEM_HALVES * (int)sizeof(__half);
    cudaFuncSetAttribute(tc_gemm_h,    cudaFuncAttributeMaxDynamicSharedMemorySize, tg_smem);
    cudaFuncSetAttribute(tc_gemm_h_b4, cudaFuncAttributeMaxDynamicSharedMemorySize, tg_smem);

    dim3 blk(256);

    // 0. fp16 weights: order r,k,v,g,o
    cvt5<<<dim3(C_ * C_ / 4 / 256, 5), blk>>>(Wr, Wk, Wv, Wg, Wo, Wh);

    // 1. prep
    prep_kernel<<<(NTOK * C_ / 4 + 255) / 256, blk>>>(x, x_maa, SX, XS);

    // 2. M1 = tanh(XS @ tm_w1)   [4096,160]  (split-K)
    splitk_gemm<<<dim3(3, 32, KS_), blk>>>(XS, C_, tm_w1, P1, NTOK, 160, C_);
    reduce_tanh<<<(NTOK * 160 + 255) / 256, blk>>>(P1, M1, NTOK * 160);

    // 3. fused mix -> WX (fp32) + KXh,VXh,RXh,GXh (fp16)
    mix_fused<<<dim3(16, 64), blk>>>(M1, tm_w2, x, SX,
                                     w_maa, k_maa, v_maa, r_maa, g_maa,
                                     WX, KXh, VXh, RXh, GXh);

    // 4. projections: batched R,K,V,G (G=silu), fp16 tensor cores
    Batch4h bp { RXh, KXh, VXh, GXh, Rb, Kb, Vb, Gb };
    tc_gemm_h_b4<<<dim3(8, 32, 4), blk, tg_smem>>>(bp, Wh, NTOK, C_, C_);

    // 5. decay LoRA: WT = tanh(WX @ td_w1) (split-K); Wd = exp(-exp(td + WT @ td_w2))
    splitk_gemm<<<dim3(1, 32, KS_), blk>>>(WX, C_, td_w1, P2, NTOK, 64, C_);
    reduce_tanh<<<(NTOK * 64 + 255) / 256, blk>>>(P2, WT, NTOK * 64);
    gemm_decay<<<dim3(8, 32), blk>>>(WT, 64, td_w2, Wd, NTOK, C_, 64, time_decay);

    // 6. chunked WKV scan, then groupnorm+gate -> fp16 Y
    scanA<<<64 * NCH, blk>>>(Rb, Kb, Vb, Wd, time_first, Yb, St, Dp);
    scanB<<<64, blk>>>(St, Dp, SIn);
    scanC<<<64 * (NCH - 1), blk>>>(Rb, Wd, SIn, Yb);
    norm_gate<<<NTOK * H_ / 8, blk>>>(Yb, Gb, ln_w, ln_b, Yh);

    // 7. output projection (fp16 tensor cores)
    tc_gemm_h<<<dim3(8, 32), blk, tg_smem>>>(Yh, Wh + 4 * (size_t)C_ * C_, out, NTOK, C_, C_);
}